// round 2
// baseline (speedup 1.0000x reference)
#include <cuda_runtime.h>
#include <math.h>

#define CDIM 256
#define NDIM 4096
#define BDIM 8

// scratch (allocation-free rule: __device__ globals)
__device__ float g_q[BDIM * NDIM * CDIM];
__device__ float g_k[BDIM * NDIM * CDIM];
__device__ float g_v[BDIM * NDIM * CDIM];

// ---------------------------------------------------------------------------
// Projection kernel: y[o,n] = sum_c W[o,c] * x[b,c,n] + bias[o]
// grid: (n_tiles=32, o_tiles=2, b*4+p=32), 256 threads, 128x128 tile, 8x8 micro
// p=0..2 -> q/k/v in [b][n][c] layout; p=3 -> proj directly into out [b][c][n]
// ---------------------------------------------------------------------------
__global__ __launch_bounds__(256) void proj_kernel(
    const float* __restrict__ x,
    const float* __restrict__ Wq, const float* __restrict__ bq,
    const float* __restrict__ Wk, const float* __restrict__ bk,
    const float* __restrict__ Wv, const float* __restrict__ bv,
    const float* __restrict__ Wp, const float* __restrict__ bp,
    float* __restrict__ out)
{
    __shared__ float sX[16 * 128];   // [cc][n]
    __shared__ float sW[16 * 128];   // [cc][o] (transposed on load)

    const int p  = blockIdx.z & 3;
    const int b  = blockIdx.z >> 2;
    const int n0 = blockIdx.x * 128;
    const int o0 = blockIdx.y * 128;

    const float* W; const float* bias;
    if (p == 0)      { W = Wq; bias = bq; }
    else if (p == 1) { W = Wk; bias = bk; }
    else if (p == 2) { W = Wv; bias = bv; }
    else             { W = Wp; bias = bp; }

    const int tid = threadIdx.x;
    const int it = tid >> 4;    // n micro: rows n0 + 8*it .. +7
    const int jt = tid & 15;    // o micro: chunks jt and jt+16 (o = 4jt+w, 64+4jt+w)

    float acc[8][8];
    #pragma unroll
    for (int r = 0; r < 8; r++)
        #pragma unroll
        for (int w = 0; w < 8; w++) acc[r][w] = 0.f;

    const float* xb = x + (size_t)b * CDIM * NDIM;

    for (int c0 = 0; c0 < CDIM; c0 += 16) {
        __syncthreads();
        // load x tile [16c][128n], coalesced float4
        #pragma unroll
        for (int q = 0; q < 2; q++) {
            int idx4 = tid + 256 * q;
            int cc  = idx4 >> 5;
            int nn4 = idx4 & 31;
            ((float4*)sX)[cc * 32 + nn4] =
                *(const float4*)(xb + (size_t)(c0 + cc) * NDIM + n0 + nn4 * 4);
        }
        // load W tile [128o][16c] -> transposed sW[cc][o]
        #pragma unroll
        for (int q = 0; q < 2; q++) {
            int idx4 = tid + 256 * q;
            int oo  = idx4 >> 2;
            int cc4 = idx4 & 3;
            float4 wv = *(const float4*)(W + (size_t)(o0 + oo) * CDIM + c0 + cc4 * 4);
            sW[(cc4 * 4 + 0) * 128 + oo] = wv.x;
            sW[(cc4 * 4 + 1) * 128 + oo] = wv.y;
            sW[(cc4 * 4 + 2) * 128 + oo] = wv.z;
            sW[(cc4 * 4 + 3) * 128 + oo] = wv.w;
        }
        __syncthreads();
        #pragma unroll
        for (int cc = 0; cc < 16; cc++) {
            float4 xa  = ((const float4*)(sX + cc * 128))[it * 2];      // broadcast
            float4 xb4 = ((const float4*)(sX + cc * 128))[it * 2 + 1];
            float4 wa  = ((const float4*)(sW + cc * 128))[jt];          // conflict-free
            float4 wb  = ((const float4*)(sW + cc * 128))[jt + 16];
            float xs[8] = {xa.x, xa.y, xa.z, xa.w, xb4.x, xb4.y, xb4.z, xb4.w};
            float ws[8] = {wa.x, wa.y, wa.z, wa.w, wb.x,  wb.y,  wb.z,  wb.w};
            #pragma unroll
            for (int r = 0; r < 8; r++)
                #pragma unroll
                for (int w = 0; w < 8; w++)
                    acc[r][w] += xs[r] * ws[w];
        }
    }

    float bias_v[8];
    #pragma unroll
    for (int w = 0; w < 8; w++) {
        int o = o0 + ((w < 4) ? (4 * jt + w) : (64 + 4 * jt + (w - 4)));
        bias_v[w] = bias[o];
    }

    if (p < 3) {
        // q/k/v layout: [b][n][c]
        float* dst = (p == 0) ? g_q : (p == 1) ? g_k : g_v;
        dst += (size_t)b * NDIM * CDIM;
        #pragma unroll
        for (int r = 0; r < 8; r++) {
            int n = n0 + it * 8 + r;
            float4 v1 = make_float4(acc[r][0] + bias_v[0], acc[r][1] + bias_v[1],
                                    acc[r][2] + bias_v[2], acc[r][3] + bias_v[3]);
            float4 v2 = make_float4(acc[r][4] + bias_v[4], acc[r][5] + bias_v[5],
                                    acc[r][6] + bias_v[6], acc[r][7] + bias_v[7]);
            *(float4*)(dst + (size_t)n * CDIM + o0 + 4 * jt)      = v1;
            *(float4*)(dst + (size_t)n * CDIM + o0 + 64 + 4 * jt) = v2;
        }
    } else {
        // proj layout: out[b][o][n] (residual base; attention adds h later)
        #pragma unroll
        for (int w = 0; w < 8; w++) {
            int o = o0 + ((w < 4) ? (4 * jt + w) : (64 + 4 * jt + (w - 4)));
            float* dst = out + ((size_t)b * CDIM + o) * NDIM + n0 + it * 8;
            float4 v1 = make_float4(acc[0][w] + bias_v[w], acc[1][w] + bias_v[w],
                                    acc[2][w] + bias_v[w], acc[3][w] + bias_v[w]);
            float4 v2 = make_float4(acc[4][w] + bias_v[w], acc[5][w] + bias_v[w],
                                    acc[6][w] + bias_v[w], acc[7][w] + bias_v[w]);
            *(float4*)(dst)     = v1;
            *(float4*)(dst + 4) = v2;
        }
    }
}

// ---------------------------------------------------------------------------
// Flash attention kernel. grid: (N/64=64 q-tiles, B=8). 256 threads.
// Per CTA: 64-row Q tile resident in smem; stream 64-row K/V tiles with
// online softmax. O accumulators in registers (4 rows x 16 cols / thread).
// Adds h into out (which already holds proj). smem = 208KB -> 1 CTA/SM.
// ---------------------------------------------------------------------------
__global__ __launch_bounds__(256, 1) void attn_kernel(float* __restrict__ out)
{
    extern __shared__ float sm[];
    float* sQ = sm;                    // [64][256]
    float* sK = sm + 64 * CDIM;        // [64][256], 16B-chunk swizzled
    float* sV = sm + 2 * 64 * CDIM;    // [64][256]
    float* sP = sm + 3 * 64 * CDIM;    // [64][64]

    const int b  = blockIdx.y;
    const int n0 = blockIdx.x * 64;
    const int tid = threadIdx.x;
    const int ti = tid >> 4;           // 0..15 -> S/O rows i0 = 4*ti
    const int tj = tid & 15;           // 0..15 -> S cols j0 = 4*tj / O col chunks
    const int i0 = ti * 4;
    const int j0 = tj * 4;
    const int xorq = tj & 7;

    const float* qb = g_q + ((size_t)b * NDIM + n0) * CDIM;
    const float* kb = g_k + (size_t)b * NDIM * CDIM;
    const float* vb = g_v + (size_t)b * NDIM * CDIM;

    // load Q tile (contiguous 64KB)
    for (int idx = tid; idx < 64 * CDIM / 4; idx += 256)
        ((float4*)sQ)[idx] = ((const float4*)qb)[idx];

    float m_run[4], l_run[4], acc[4][16];
    #pragma unroll
    for (int r = 0; r < 4; r++) {
        m_run[r] = -INFINITY; l_run[r] = 0.f;
        #pragma unroll
        for (int c = 0; c < 16; c++) acc[r][c] = 0.f;
    }

    for (int m0 = 0; m0 < NDIM; m0 += 64) {
        __syncthreads();   // prev PV reads of sK/sV/sP done
        // load K (swizzled) + V tiles, coalesced 512B per warp-instr
        for (int idx = tid; idx < 64 * 64; idx += 256) {
            int row = idx >> 6, kc = idx & 63;
            float4 kv4 = *(const float4*)(kb + (size_t)(m0 + row) * CDIM + kc * 4);
            float4 vv4 = *(const float4*)(vb + (size_t)(m0 + row) * CDIM + kc * 4);
            ((float4*)(sK + row * CDIM))[kc ^ ((row >> 2) & 7)] = kv4;
            ((float4*)(sV + row * CDIM))[kc] = vv4;
        }
        __syncthreads();

        // S = Q K^T : 4x4 micro per thread
        float s[4][4];
        #pragma unroll
        for (int r = 0; r < 4; r++)
            #pragma unroll
            for (int jr = 0; jr < 4; jr++) s[r][jr] = 0.f;

        for (int c4 = 0; c4 < 64; c4++) {
            float4 kv[4];
            int pc = c4 ^ xorq;
            #pragma unroll
            for (int jr = 0; jr < 4; jr++)
                kv[jr] = ((const float4*)(sK + (j0 + jr) * CDIM))[pc];
            #pragma unroll
            for (int r = 0; r < 4; r++) {
                float4 qv = ((const float4*)(sQ + (i0 + r) * CDIM))[c4]; // broadcast
                #pragma unroll
                for (int jr = 0; jr < 4; jr++)
                    s[r][jr] += qv.x * kv[jr].x + qv.y * kv[jr].y
                              + qv.z * kv[jr].z + qv.w * kv[jr].w;
            }
        }

        // online softmax (row stats shared across the 16-lane half-warp)
        #pragma unroll
        for (int r = 0; r < 4; r++) {
            float sv[4];
            float mloc = -INFINITY;
            #pragma unroll
            for (int jr = 0; jr < 4; jr++) {
                sv[jr] = s[r][jr] * 0.0625f;       // scale = C^-0.5 = 1/16
                mloc = fmaxf(mloc, sv[jr]);
            }
            #pragma unroll
            for (int o = 8; o > 0; o >>= 1)
                mloc = fmaxf(mloc, __shfl_xor_sync(0xffffffffu, mloc, o));
            float mn = fmaxf(m_run[r], mloc);
            float alpha = __expf(m_run[r] - mn);   // 0 on first tile
            m_run[r] = mn;
            float pr[4], lloc = 0.f;
            #pragma unroll
            for (int jr = 0; jr < 4; jr++) { pr[jr] = __expf(sv[jr] - mn); lloc += pr[jr]; }
            #pragma unroll
            for (int o = 8; o > 0; o >>= 1)
                lloc += __shfl_xor_sync(0xffffffffu, lloc, o);
            l_run[r] = l_run[r] * alpha + lloc;
            #pragma unroll
            for (int c = 0; c < 16; c++) acc[r][c] *= alpha;
            *(float4*)(sP + (i0 + r) * 64 + j0) = make_float4(pr[0], pr[1], pr[2], pr[3]);
        }
        __syncthreads();

        // O += P V : rows i0..i0+3, col chunks tj + 16*kk (conflict-free)
        for (int j = 0; j < 64; j++) {
            float p0 = sP[(i0 + 0) * 64 + j];      // broadcast
            float p1 = sP[(i0 + 1) * 64 + j];
            float p2 = sP[(i0 + 2) * 64 + j];
            float p3 = sP[(i0 + 3) * 64 + j];
            #pragma unroll
            for (int kk = 0; kk < 4; kk++) {
                float4 vv = ((const float4*)(sV + j * CDIM))[tj + 16 * kk];
                acc[0][kk * 4 + 0] += p0 * vv.x; acc[0][kk * 4 + 1] += p0 * vv.y;
                acc[0][kk * 4 + 2] += p0 * vv.z; acc[0][kk * 4 + 3] += p0 * vv.w;
                acc[1][kk * 4 + 0] += p1 * vv.x; acc[1][kk * 4 + 1] += p1 * vv.y;
                acc[1][kk * 4 + 2] += p1 * vv.z; acc[1][kk * 4 + 3] += p1 * vv.w;
                acc[2][kk * 4 + 0] += p2 * vv.x; acc[2][kk * 4 + 1] += p2 * vv.y;
                acc[2][kk * 4 + 2] += p2 * vv.z; acc[2][kk * 4 + 3] += p2 * vv.w;
                acc[3][kk * 4 + 0] += p3 * vv.x; acc[3][kk * 4 + 1] += p3 * vv.y;
                acc[3][kk * 4 + 2] += p3 * vv.z; acc[3][kk * 4 + 3] += p3 * vv.w;
            }
        }
    }

    // epilogue: h = O / l, out[b][c][n0+i] += h (4 consecutive n per float4)
    float inv[4];
    #pragma unroll
    for (int r = 0; r < 4; r++) inv[r] = 1.0f / l_run[r];
    float* ob = out + (size_t)b * CDIM * NDIM + n0;
    #pragma unroll
    for (int kk = 0; kk < 4; kk++) {
        #pragma unroll
        for (int w = 0; w < 4; w++) {
            int c = 4 * (tj + 16 * kk) + w;
            float4* dst = (float4*)(ob + (size_t)c * NDIM + i0);
            float4 o4 = *dst;
            o4.x += acc[0][kk * 4 + w] * inv[0];
            o4.y += acc[1][kk * 4 + w] * inv[1];
            o4.z += acc[2][kk * 4 + w] * inv[2];
            o4.w += acc[3][kk * 4 + w] * inv[3];
            *dst = o4;
        }
    }
}

extern "C" void kernel_launch(void* const* d_in, const int* in_sizes, int n_in,
                              void* d_out, int out_size)
{
    const float* x  = (const float*)d_in[0];
    const float* Wq = (const float*)d_in[1];
    const float* bq = (const float*)d_in[2];
    const float* Wk = (const float*)d_in[3];
    const float* bk = (const float*)d_in[4];
    const float* Wv = (const float*)d_in[5];
    const float* bv = (const float*)d_in[6];
    const float* Wp = (const float*)d_in[7];
    const float* bp = (const float*)d_in[8];
    float* out = (float*)d_out;

    // 208KB dynamic smem for the attention kernel (idempotent, capture-safe)
    cudaFuncSetAttribute(attn_kernel,
                         cudaFuncAttributeMaxDynamicSharedMemorySize, 212992);

    // 1) q/k/v into scratch + proj into out (residual base)
    proj_kernel<<<dim3(32, 2, 32), 256>>>(x, Wq, bq, Wk, bk, Wv, bv, Wp, bp, out);
    // 2) flash attention, h accumulated into out
    attn_kernel<<<dim3(64, 8), 256, 212992>>>(out);
}

// round 3
// speedup vs baseline: 1.0025x; 1.0025x over previous
#include <cuda_runtime.h>
#include <math.h>

#define CDIM 256
#define NDIM 4096
#define BDIM 8

// scratch (allocation-free rule: __device__ globals)
__device__ float g_q[BDIM * NDIM * CDIM];
__device__ float g_k[BDIM * NDIM * CDIM];
__device__ float g_v[BDIM * NDIM * CDIM];

// ---------------------------------------------------------------------------
// Projection kernel: y[o,n] = sum_c W[o,c] * x[b,c,n] + bias[o]
// grid: (n_tiles=32, o_tiles=2, b*4+p=32), 256 threads, 128x128 tile, 8x8 micro
// p=0..2 -> q/k/v in [b][n][c] layout; p=3 -> proj directly into out [b][c][n]
// ---------------------------------------------------------------------------
__global__ __launch_bounds__(256) void proj_kernel(
    const float* __restrict__ x,
    const float* __restrict__ Wq, const float* __restrict__ bq,
    const float* __restrict__ Wk, const float* __restrict__ bk,
    const float* __restrict__ Wv, const float* __restrict__ bv,
    const float* __restrict__ Wp, const float* __restrict__ bp,
    float* __restrict__ out)
{
    __shared__ float sX[16 * 128];   // [cc][n]
    __shared__ float sW[16 * 128];   // [cc][o] (transposed on load)

    const int p  = blockIdx.z & 3;
    const int b  = blockIdx.z >> 2;
    const int n0 = blockIdx.x * 128;
    const int o0 = blockIdx.y * 128;

    const float* W; const float* bias;
    if (p == 0)      { W = Wq; bias = bq; }
    else if (p == 1) { W = Wk; bias = bk; }
    else if (p == 2) { W = Wv; bias = bv; }
    else             { W = Wp; bias = bp; }

    const int tid = threadIdx.x;
    const int it = tid >> 4;    // n micro: rows n0 + 8*it .. +7
    const int jt = tid & 15;    // o micro: chunks jt and jt+16 (o = 4jt+w, 64+4jt+w)

    float acc[8][8];
    #pragma unroll
    for (int r = 0; r < 8; r++)
        #pragma unroll
        for (int w = 0; w < 8; w++) acc[r][w] = 0.f;

    const float* xb = x + (size_t)b * CDIM * NDIM;

    for (int c0 = 0; c0 < CDIM; c0 += 16) {
        __syncthreads();
        // load x tile [16c][128n], coalesced float4
        #pragma unroll
        for (int q = 0; q < 2; q++) {
            int idx4 = tid + 256 * q;
            int cc  = idx4 >> 5;
            int nn4 = idx4 & 31;
            ((float4*)sX)[cc * 32 + nn4] =
                *(const float4*)(xb + (size_t)(c0 + cc) * NDIM + n0 + nn4 * 4);
        }
        // load W tile [128o][16c] -> transposed sW[cc][o]
        #pragma unroll
        for (int q = 0; q < 2; q++) {
            int idx4 = tid + 256 * q;
            int oo  = idx4 >> 2;
            int cc4 = idx4 & 3;
            float4 wv = *(const float4*)(W + (size_t)(o0 + oo) * CDIM + c0 + cc4 * 4);
            sW[(cc4 * 4 + 0) * 128 + oo] = wv.x;
            sW[(cc4 * 4 + 1) * 128 + oo] = wv.y;
            sW[(cc4 * 4 + 2) * 128 + oo] = wv.z;
            sW[(cc4 * 4 + 3) * 128 + oo] = wv.w;
        }
        __syncthreads();
        #pragma unroll
        for (int cc = 0; cc < 16; cc++) {
            float4 xa  = ((const float4*)(sX + cc * 128))[it * 2];      // broadcast
            float4 xb4 = ((const float4*)(sX + cc * 128))[it * 2 + 1];
            float4 wa  = ((const float4*)(sW + cc * 128))[jt];          // conflict-free
            float4 wb  = ((const float4*)(sW + cc * 128))[jt + 16];
            float xs[8] = {xa.x, xa.y, xa.z, xa.w, xb4.x, xb4.y, xb4.z, xb4.w};
            float ws[8] = {wa.x, wa.y, wa.z, wa.w, wb.x,  wb.y,  wb.z,  wb.w};
            #pragma unroll
            for (int r = 0; r < 8; r++)
                #pragma unroll
                for (int w = 0; w < 8; w++)
                    acc[r][w] += xs[r] * ws[w];
        }
    }

    float bias_v[8];
    #pragma unroll
    for (int w = 0; w < 8; w++) {
        int o = o0 + ((w < 4) ? (4 * jt + w) : (64 + 4 * jt + (w - 4)));
        bias_v[w] = bias[o];
    }

    if (p < 3) {
        // q/k/v layout: [b][n][c]
        float* dst = (p == 0) ? g_q : (p == 1) ? g_k : g_v;
        dst += (size_t)b * NDIM * CDIM;
        #pragma unroll
        for (int r = 0; r < 8; r++) {
            int n = n0 + it * 8 + r;
            float4 v1 = make_float4(acc[r][0] + bias_v[0], acc[r][1] + bias_v[1],
                                    acc[r][2] + bias_v[2], acc[r][3] + bias_v[3]);
            float4 v2 = make_float4(acc[r][4] + bias_v[4], acc[r][5] + bias_v[5],
                                    acc[r][6] + bias_v[6], acc[r][7] + bias_v[7]);
            *(float4*)(dst + (size_t)n * CDIM + o0 + 4 * jt)      = v1;
            *(float4*)(dst + (size_t)n * CDIM + o0 + 64 + 4 * jt) = v2;
        }
    } else {
        // proj layout: out[b][o][n] (residual base; attention adds h later)
        #pragma unroll
        for (int w = 0; w < 8; w++) {
            int o = o0 + ((w < 4) ? (4 * jt + w) : (64 + 4 * jt + (w - 4)));
            float* dst = out + ((size_t)b * CDIM + o) * NDIM + n0 + it * 8;
            float4 v1 = make_float4(acc[0][w] + bias_v[w], acc[1][w] + bias_v[w],
                                    acc[2][w] + bias_v[w], acc[3][w] + bias_v[w]);
            float4 v2 = make_float4(acc[4][w] + bias_v[w], acc[5][w] + bias_v[w],
                                    acc[6][w] + bias_v[w], acc[7][w] + bias_v[w]);
            *(float4*)(dst)     = v1;
            *(float4*)(dst + 4) = v2;
        }
    }
}

// ---------------------------------------------------------------------------
// Flash attention kernel. grid: (N/64=64 q-tiles, B=8). 256 threads.
// Per CTA: 64-row Q tile resident in smem; stream 64-row K/V tiles with
// online softmax. O accumulators in registers (4 rows x 16 cols / thread).
// Adds h into out (which already holds proj). smem = 208KB -> 1 CTA/SM.
// ---------------------------------------------------------------------------
__global__ __launch_bounds__(256, 1) void attn_kernel(float* __restrict__ out)
{
    extern __shared__ float sm[];
    float* sQ = sm;                    // [64][256]
    float* sK = sm + 64 * CDIM;        // [64][256], 16B-chunk swizzled
    float* sV = sm + 2 * 64 * CDIM;    // [64][256]
    float* sP = sm + 3 * 64 * CDIM;    // [64][64]

    const int b  = blockIdx.y;
    const int n0 = blockIdx.x * 64;
    const int tid = threadIdx.x;
    const int ti = tid >> 4;           // 0..15 -> S/O rows i0 = 4*ti
    const int tj = tid & 15;           // 0..15 -> S cols j0 = 4*tj / O col chunks
    const int i0 = ti * 4;
    const int j0 = tj * 4;
    const int xorq = tj & 7;

    const float* qb = g_q + ((size_t)b * NDIM + n0) * CDIM;
    const float* kb = g_k + (size_t)b * NDIM * CDIM;
    const float* vb = g_v + (size_t)b * NDIM * CDIM;

    // load Q tile (contiguous 64KB)
    for (int idx = tid; idx < 64 * CDIM / 4; idx += 256)
        ((float4*)sQ)[idx] = ((const float4*)qb)[idx];

    float m_run[4], l_run[4], acc[4][16];
    #pragma unroll
    for (int r = 0; r < 4; r++) {
        m_run[r] = -INFINITY; l_run[r] = 0.f;
        #pragma unroll
        for (int c = 0; c < 16; c++) acc[r][c] = 0.f;
    }

    for (int m0 = 0; m0 < NDIM; m0 += 64) {
        __syncthreads();   // prev PV reads of sK/sV/sP done
        // load K (swizzled) + V tiles, coalesced 512B per warp-instr
        for (int idx = tid; idx < 64 * 64; idx += 256) {
            int row = idx >> 6, kc = idx & 63;
            float4 kv4 = *(const float4*)(kb + (size_t)(m0 + row) * CDIM + kc * 4);
            float4 vv4 = *(const float4*)(vb + (size_t)(m0 + row) * CDIM + kc * 4);
            ((float4*)(sK + row * CDIM))[kc ^ ((row >> 2) & 7)] = kv4;
            ((float4*)(sV + row * CDIM))[kc] = vv4;
        }
        __syncthreads();

        // S = Q K^T : 4x4 micro per thread
        float s[4][4];
        #pragma unroll
        for (int r = 0; r < 4; r++)
            #pragma unroll
            for (int jr = 0; jr < 4; jr++) s[r][jr] = 0.f;

        for (int c4 = 0; c4 < 64; c4++) {
            float4 kv[4];
            int pc = c4 ^ xorq;
            #pragma unroll
            for (int jr = 0; jr < 4; jr++)
                kv[jr] = ((const float4*)(sK + (j0 + jr) * CDIM))[pc];
            #pragma unroll
            for (int r = 0; r < 4; r++) {
                float4 qv = ((const float4*)(sQ + (i0 + r) * CDIM))[c4]; // broadcast
                #pragma unroll
                for (int jr = 0; jr < 4; jr++)
                    s[r][jr] += qv.x * kv[jr].x + qv.y * kv[jr].y
                              + qv.z * kv[jr].z + qv.w * kv[jr].w;
            }
        }

        // online softmax (row stats shared across the 16-lane half-warp)
        #pragma unroll
        for (int r = 0; r < 4; r++) {
            float sv[4];
            float mloc = -INFINITY;
            #pragma unroll
            for (int jr = 0; jr < 4; jr++) {
                sv[jr] = s[r][jr] * 0.0625f;       // scale = C^-0.5 = 1/16
                mloc = fmaxf(mloc, sv[jr]);
            }
            #pragma unroll
            for (int o = 8; o > 0; o >>= 1)
                mloc = fmaxf(mloc, __shfl_xor_sync(0xffffffffu, mloc, o));
            float mn = fmaxf(m_run[r], mloc);
            float alpha = __expf(m_run[r] - mn);   // 0 on first tile
            m_run[r] = mn;
            float pr[4], lloc = 0.f;
            #pragma unroll
            for (int jr = 0; jr < 4; jr++) { pr[jr] = __expf(sv[jr] - mn); lloc += pr[jr]; }
            #pragma unroll
            for (int o = 8; o > 0; o >>= 1)
                lloc += __shfl_xor_sync(0xffffffffu, lloc, o);
            l_run[r] = l_run[r] * alpha + lloc;
            #pragma unroll
            for (int c = 0; c < 16; c++) acc[r][c] *= alpha;
            *(float4*)(sP + (i0 + r) * 64 + j0) = make_float4(pr[0], pr[1], pr[2], pr[3]);
        }
        __syncthreads();

        // O += P V : rows i0..i0+3, col chunks tj + 16*kk (conflict-free)
        for (int j = 0; j < 64; j++) {
            float p0 = sP[(i0 + 0) * 64 + j];      // broadcast
            float p1 = sP[(i0 + 1) * 64 + j];
            float p2 = sP[(i0 + 2) * 64 + j];
            float p3 = sP[(i0 + 3) * 64 + j];
            #pragma unroll
            for (int kk = 0; kk < 4; kk++) {
                float4 vv = ((const float4*)(sV + j * CDIM))[tj + 16 * kk];
                acc[0][kk * 4 + 0] += p0 * vv.x; acc[0][kk * 4 + 1] += p0 * vv.y;
                acc[0][kk * 4 + 2] += p0 * vv.z; acc[0][kk * 4 + 3] += p0 * vv.w;
                acc[1][kk * 4 + 0] += p1 * vv.x; acc[1][kk * 4 + 1] += p1 * vv.y;
                acc[1][kk * 4 + 2] += p1 * vv.z; acc[1][kk * 4 + 3] += p1 * vv.w;
                acc[2][kk * 4 + 0] += p2 * vv.x; acc[2][kk * 4 + 1] += p2 * vv.y;
                acc[2][kk * 4 + 2] += p2 * vv.z; acc[2][kk * 4 + 3] += p2 * vv.w;
                acc[3][kk * 4 + 0] += p3 * vv.x; acc[3][kk * 4 + 1] += p3 * vv.y;
                acc[3][kk * 4 + 2] += p3 * vv.z; acc[3][kk * 4 + 3] += p3 * vv.w;
            }
        }
    }

    // epilogue: h = O / l, out[b][c][n0+i] += h (4 consecutive n per float4)
    float inv[4];
    #pragma unroll
    for (int r = 0; r < 4; r++) inv[r] = 1.0f / l_run[r];
    float* ob = out + (size_t)b * CDIM * NDIM + n0;
    #pragma unroll
    for (int kk = 0; kk < 4; kk++) {
        #pragma unroll
        for (int w = 0; w < 4; w++) {
            int c = 4 * (tj + 16 * kk) + w;
            float4* dst = (float4*)(ob + (size_t)c * NDIM + i0);
            float4 o4 = *dst;
            o4.x += acc[0][kk * 4 + w] * inv[0];
            o4.y += acc[1][kk * 4 + w] * inv[1];
            o4.z += acc[2][kk * 4 + w] * inv[2];
            o4.w += acc[3][kk * 4 + w] * inv[3];
            *dst = o4;
        }
    }
}

extern "C" void kernel_launch(void* const* d_in, const int* in_sizes, int n_in,
                              void* d_out, int out_size)
{
    const float* x  = (const float*)d_in[0];
    const float* Wq = (const float*)d_in[1];
    const float* bq = (const float*)d_in[2];
    const float* Wk = (const float*)d_in[3];
    const float* bk = (const float*)d_in[4];
    const float* Wv = (const float*)d_in[5];
    const float* bv = (const float*)d_in[6];
    const float* Wp = (const float*)d_in[7];
    const float* bp = (const float*)d_in[8];
    float* out = (float*)d_out;

    // 208KB dynamic smem for the attention kernel (idempotent, capture-safe)
    cudaFuncSetAttribute(attn_kernel,
                         cudaFuncAttributeMaxDynamicSharedMemorySize, 212992);

    // 1) q/k/v into scratch + proj into out (residual base)
    proj_kernel<<<dim3(32, 2, 32), 256>>>(x, Wq, bq, Wk, bk, Wv, bv, Wp, bp, out);
    // 2) flash attention, h accumulated into out
    attn_kernel<<<dim3(64, 8), 256, 212992>>>(out);
}

// round 5
// speedup vs baseline: 2.7812x; 2.7743x over previous
#include <cuda_runtime.h>
#include <math.h>
#include <stdint.h>

#define CDIM 256
#define NDIM 4096
#define BDIM 8
#define QR   64
#define TK   32
#define NT   (NDIM / TK)   // 128

__device__ float g_q[(size_t)BDIM * NDIM * CDIM];   // [b][n][c] tf32
__device__ float g_k[(size_t)BDIM * NDIM * CDIM];   // [b][n][c] tf32
__device__ float g_v[(size_t)BDIM * NDIM * CDIM];   // [b][c][n] tf32 (transposed)

// ---- smem layout (float offsets); all strides == 4 mod 32 -> conflict-free frags
#define SQ_OFF 0
#define SQ_STR 260
#define SK_OFF (SQ_OFF + QR * SQ_STR)          // 16640
#define SK_STR 260
#define SK_BUF (TK * SK_STR)                   // 8320
#define SV_OFF (SK_OFF + 2 * SK_BUF)           // 33280
#define SV_STR 36
#define SV_BUF (CDIM * SV_STR)                 // 9216
#define SP_OFF (SV_OFF + 2 * SV_BUF)           // 51712
#define SP_STR 36
#define SL_OFF (SP_OFF + QR * SP_STR)          // 54016
#define SM_TOT (SL_OFF + 2 * QR)               // 54144 floats = 216576 B

// ---------------- helpers ----------------
__device__ __forceinline__ uint32_t smem_u32(const void* p) {
    uint32_t a;
    asm("{ .reg .u64 t; cvta.to.shared.u64 t, %1; cvt.u32.u64 %0, t; }" : "=r"(a) : "l"(p));
    return a;
}
__device__ __forceinline__ float to_tf32(float x) {
    float r; asm("cvt.rna.tf32.f32 %0, %1;" : "=f"(r) : "f"(x)); return r;
}
__device__ __forceinline__ float ex2(float x) {
    float y; asm("ex2.approx.f32 %0, %1;" : "=f"(y) : "f"(x)); return y;
}
__device__ __forceinline__ void cp16(uint32_t saddr, const void* gaddr) {
    asm volatile("cp.async.cg.shared.global [%0], [%1], 16;" :: "r"(saddr), "l"(gaddr));
}
__device__ __forceinline__ void cp_commit() {
    asm volatile("cp.async.commit_group;" ::: "memory");
}
template <int N>
__device__ __forceinline__ void cp_wait() {
    asm volatile("cp.async.wait_group %0;" :: "n"(N) : "memory");
}
// m16n8k8 tf32 mma: a0=[g][t] a1=[g+8][t] a2=[g][t+4] a3=[g+8][t+4];
// b0=[k=t][n=g] b1=[k=t+4][n=g]; d: c0=[g][2t] c1=[g][2t+1] c2=[g+8][2t] c3=[g+8][2t+1]
__device__ __forceinline__ void mma8(float* d, float a0, float a1, float a2, float a3,
                                     float b0, float b1) {
    asm volatile("mma.sync.aligned.m16n8k8.row.col.f32.tf32.tf32.f32 "
        "{%0,%1,%2,%3}, {%4,%5,%6,%7}, {%8,%9}, {%0,%1,%2,%3};"
        : "+f"(d[0]), "+f"(d[1]), "+f"(d[2]), "+f"(d[3])
        : "r"(__float_as_uint(a0)), "r"(__float_as_uint(a1)),
          "r"(__float_as_uint(a2)), "r"(__float_as_uint(a3)),
          "r"(__float_as_uint(b0)), "r"(__float_as_uint(b1)));
}

// ---------------- projection (fp32 CUDA cores) ----------------
__global__ __launch_bounds__(256) void proj_kernel(
    const float* __restrict__ x,
    const float* __restrict__ Wq, const float* __restrict__ bq,
    const float* __restrict__ Wk, const float* __restrict__ bk,
    const float* __restrict__ Wv, const float* __restrict__ bv,
    const float* __restrict__ Wp, const float* __restrict__ bp,
    float* __restrict__ out)
{
    __shared__ float sX[16 * 128];
    __shared__ float sW[16 * 128];
    const int p  = blockIdx.z & 3;
    const int b  = blockIdx.z >> 2;
    const int n0 = blockIdx.x * 128;
    const int o0 = blockIdx.y * 128;
    const float* W; const float* bias;
    if (p == 0)      { W = Wq; bias = bq; }
    else if (p == 1) { W = Wk; bias = bk; }
    else if (p == 2) { W = Wv; bias = bv; }
    else             { W = Wp; bias = bp; }
    const int tid = threadIdx.x, it = tid >> 4, jt = tid & 15;

    float acc[8][8];
    #pragma unroll
    for (int r = 0; r < 8; r++)
        #pragma unroll
        for (int w = 0; w < 8; w++) acc[r][w] = 0.f;
    const float* xb = x + (size_t)b * CDIM * NDIM;

    for (int c0 = 0; c0 < CDIM; c0 += 16) {
        __syncthreads();
        #pragma unroll
        for (int q = 0; q < 2; q++) {
            int idx4 = tid + 256 * q, cc = idx4 >> 5, nn4 = idx4 & 31;
            ((float4*)sX)[cc * 32 + nn4] =
                *(const float4*)(xb + (size_t)(c0 + cc) * NDIM + n0 + nn4 * 4);
        }
        #pragma unroll
        for (int q = 0; q < 2; q++) {
            int idx4 = tid + 256 * q, oo = idx4 >> 2, cc4 = idx4 & 3;
            float4 wv = *(const float4*)(W + (size_t)(o0 + oo) * CDIM + c0 + cc4 * 4);
            sW[(cc4 * 4 + 0) * 128 + oo] = wv.x;
            sW[(cc4 * 4 + 1) * 128 + oo] = wv.y;
            sW[(cc4 * 4 + 2) * 128 + oo] = wv.z;
            sW[(cc4 * 4 + 3) * 128 + oo] = wv.w;
        }
        __syncthreads();
        #pragma unroll
        for (int cc = 0; cc < 16; cc++) {
            float4 xa  = ((const float4*)(sX + cc * 128))[it * 2];
            float4 xb4 = ((const float4*)(sX + cc * 128))[it * 2 + 1];
            float4 wa  = ((const float4*)(sW + cc * 128))[jt];
            float4 wb  = ((const float4*)(sW + cc * 128))[jt + 16];
            float xs[8] = {xa.x, xa.y, xa.z, xa.w, xb4.x, xb4.y, xb4.z, xb4.w};
            float ws[8] = {wa.x, wa.y, wa.z, wa.w, wb.x,  wb.y,  wb.z,  wb.w};
            #pragma unroll
            for (int r = 0; r < 8; r++)
                #pragma unroll
                for (int w = 0; w < 8; w++) acc[r][w] += xs[r] * ws[w];
        }
    }
    float bias_v[8];
    #pragma unroll
    for (int w = 0; w < 8; w++) {
        int o = o0 + ((w < 4) ? (4 * jt + w) : (64 + 4 * jt + (w - 4)));
        bias_v[w] = bias[o];
    }
    if (p < 2) {   // q/k: [b][n][c], tf32-rounded
        float* dst = ((p == 0) ? g_q : g_k) + (size_t)b * NDIM * CDIM;
        #pragma unroll
        for (int r = 0; r < 8; r++) {
            int n = n0 + it * 8 + r;
            float4 v1 = make_float4(to_tf32(acc[r][0]+bias_v[0]), to_tf32(acc[r][1]+bias_v[1]),
                                    to_tf32(acc[r][2]+bias_v[2]), to_tf32(acc[r][3]+bias_v[3]));
            float4 v2 = make_float4(to_tf32(acc[r][4]+bias_v[4]), to_tf32(acc[r][5]+bias_v[5]),
                                    to_tf32(acc[r][6]+bias_v[6]), to_tf32(acc[r][7]+bias_v[7]));
            *(float4*)(dst + (size_t)n * CDIM + o0 + 4 * jt)      = v1;
            *(float4*)(dst + (size_t)n * CDIM + o0 + 64 + 4 * jt) = v2;
        }
    } else {       // v (tf32) and proj: [b][o][n]
        float* dstb = (p == 2) ? (g_v + (size_t)b * CDIM * NDIM)
                               : (out + (size_t)b * CDIM * NDIM);
        #pragma unroll
        for (int w = 0; w < 8; w++) {
            int o = o0 + ((w < 4) ? (4 * jt + w) : (64 + 4 * jt + (w - 4)));
            float* dst = dstb + (size_t)o * NDIM + n0 + it * 8;
            float4 v1 = make_float4(acc[0][w]+bias_v[w], acc[1][w]+bias_v[w],
                                    acc[2][w]+bias_v[w], acc[3][w]+bias_v[w]);
            float4 v2 = make_float4(acc[4][w]+bias_v[w], acc[5][w]+bias_v[w],
                                    acc[6][w]+bias_v[w], acc[7][w]+bias_v[w]);
            if (p == 2) {
                v1 = make_float4(to_tf32(v1.x), to_tf32(v1.y), to_tf32(v1.z), to_tf32(v1.w));
                v2 = make_float4(to_tf32(v2.x), to_tf32(v2.y), to_tf32(v2.z), to_tf32(v2.w));
            }
            *(float4*)(dst)     = v1;
            *(float4*)(dst + 4) = v2;
        }
    }
}

// ---------------- K/V tile loader (cp.async, 16 x 16B per thread) ----------
__device__ __forceinline__ void load_tile(float* sm, const float* kb, const float* vb,
                                          int i, int buf, int tid)
{
    const int m0 = i * TK;
    const uint32_t skb = smem_u32(sm + SK_OFF + buf * SK_BUF);
    const uint32_t svb = smem_u32(sm + SV_OFF + buf * SV_BUF);
    #pragma unroll
    for (int j = 0; j < 8; j++) {            // K: 32 keys x 256 c
        int idx = tid + 256 * j;
        int r = idx >> 6, c4 = idx & 63;
        cp16(skb + (uint32_t)(r * SK_STR + 4 * c4) * 4u,
             kb + (size_t)(m0 + r) * CDIM + 4 * c4);
    }
    #pragma unroll
    for (int j = 0; j < 8; j++) {            // V^T: 256 c x 32 keys
        int idx = tid + 256 * j;
        int r = idx >> 3, c4 = idx & 7;
        cp16(svb + (uint32_t)(r * SV_STR + 4 * c4) * 4u,
             vb + (size_t)r * NDIM + m0 + 4 * c4);
    }
}

// ---------------- mma.sync tf32 flash attention ----------------------------
// grid (64, 8), 256 thr, 8 warps: S warp grid 4M x 2N (tile 16x16),
// PV warp tile 16 x 128 over all 32 keys. H in 64 regs/thread.
__global__ __launch_bounds__(256, 1) void attn_kernel(float* __restrict__ out)
{
    extern __shared__ float sm[];
    const int tid  = threadIdx.x;
    const int w    = tid >> 5;
    const int lane = tid & 31;
    const int g    = lane >> 2;      // groupID 0..7
    const int t    = lane & 3;       // threadID_in_group
    const int wm   = w >> 1;         // 0..3: q-row block 16*wm
    const int wn   = w & 1;          // 0..1
    const int b    = blockIdx.y;
    const int n0   = blockIdx.x * QR;

    const float* qb = g_q + ((size_t)b * NDIM + n0) * CDIM;
    const float* kb = g_k + (size_t)b * NDIM * CDIM;
    const float* vb = g_v + (size_t)b * CDIM * NDIM;

    load_tile(sm, kb, vb, 0, 0, tid);        // prologue tile 0
    cp_commit();

    for (int idx = tid; idx < QR * 64; idx += 256) {   // Q tile
        int r = idx >> 6, c4 = idx & 63;
        *(float4*)(sm + SQ_OFF + r * SQ_STR + 4 * c4) =
            *(const float4*)(qb + (size_t)r * CDIM + 4 * c4);
    }

    float hacc[16][4];
    #pragma unroll
    for (int nf = 0; nf < 16; nf++)
        #pragma unroll
        for (int k = 0; k < 4; k++) hacc[nf][k] = 0.f;
    float lsum0 = 0.f, lsum1 = 0.f;
    const float EC = 0.0901684400555602f;    // log2(e)/16

    for (int i = 0; i < NT; i++) {
        const int buf = i & 1;
        if (i + 1 < NT) { load_tile(sm, kb, vb, i + 1, (i + 1) & 1, tid); cp_commit(); cp_wait<1>(); }
        else            { cp_wait<0>(); }
        __syncthreads();

        // ---- S = Q K^T, warp tile 16x16 ----
        float sacc[2][4] = {{0.f,0.f,0.f,0.f},{0.f,0.f,0.f,0.f}};
        const float* qA  = sm + SQ_OFF + (16 * wm + g) * SQ_STR;
        const float* qB  = qA + 8 * SQ_STR;
        const float* kT0 = sm + SK_OFF + buf * SK_BUF + (16 * wn + g) * SK_STR;
        const float* kT1 = kT0 + 8 * SK_STR;
        #pragma unroll 8
        for (int ks = 0; ks < 32; ks++) {
            int c0 = 8 * ks + t;
            float a0 = qA[c0], a1 = qB[c0], a2 = qA[c0 + 4], a3 = qB[c0 + 4];
            mma8(sacc[0], a0, a1, a2, a3, kT0[c0], kT0[c0 + 4]);
            mma8(sacc[1], a0, a1, a2, a3, kT1[c0], kT1[c0 + 4]);
        }

        // ---- softmax (max-free), write P, accumulate l ----
        float* pr0 = sm + SP_OFF + (16 * wm + g) * SP_STR + 16 * wn;
        float* pr1 = pr0 + 8 * SP_STR;
        #pragma unroll
        for (int nf = 0; nf < 2; nf++) {
            float p0 = to_tf32(ex2(sacc[nf][0] * EC));
            float p1 = to_tf32(ex2(sacc[nf][1] * EC));
            float p2 = to_tf32(ex2(sacc[nf][2] * EC));
            float p3 = to_tf32(ex2(sacc[nf][3] * EC));
            lsum0 += p0 + p1;
            lsum1 += p2 + p3;
            *(float2*)(pr0 + nf * 8 + 2 * t) = make_float2(p0, p1);
            *(float2*)(pr1 + nf * 8 + 2 * t) = make_float2(p2, p3);
        }
        __syncthreads();

        // ---- H += P V, warp tile 16 x 128 ----
        const float* pA = sm + SP_OFF + (16 * wm + g) * SP_STR;
        const float* pB = pA + 8 * SP_STR;
        const float* vT = sm + SV_OFF + buf * SV_BUF + (wn * 128 + g) * SV_STR;
        #pragma unroll
        for (int ks = 0; ks < 4; ks++) {
            int k0 = 8 * ks + t;
            float a0 = pA[k0], a1 = pB[k0], a2 = pA[k0 + 4], a3 = pB[k0 + 4];
            #pragma unroll
            for (int nf = 0; nf < 16; nf++) {
                const float* vr = vT + nf * 8 * SV_STR;
                mma8(hacc[nf], a0, a1, a2, a3, vr[k0], vr[k0 + 4]);
            }
        }
        __syncthreads();
    }

    // ---- l reduction (over t lanes, then the 2 wn warps via smem) ----
    lsum0 += __shfl_xor_sync(0xffffffffu, lsum0, 1);
    lsum0 += __shfl_xor_sync(0xffffffffu, lsum0, 2);
    lsum1 += __shfl_xor_sync(0xffffffffu, lsum1, 1);
    lsum1 += __shfl_xor_sync(0xffffffffu, lsum1, 2);
    if (t == 0) {
        sm[SL_OFF + wn * QR + 16 * wm + g]     = lsum0;
        sm[SL_OFF + wn * QR + 16 * wm + 8 + g] = lsum1;
    }
    __syncthreads();
    const int r0 = 16 * wm + g;
    float li0 = 1.f / (sm[SL_OFF + r0]     + sm[SL_OFF + QR + r0]);
    float li1 = 1.f / (sm[SL_OFF + r0 + 8] + sm[SL_OFF + QR + r0 + 8]);

    // ---- epilogue: out[b][c][n] += h / l ----
    float* ob = out + (size_t)b * CDIM * NDIM + n0;
    #pragma unroll
    for (int nf = 0; nf < 16; nf++) {
        int c = wn * 128 + nf * 8 + 2 * t;
        float* d0 = ob + (size_t)c * NDIM + r0;
        float* d1 = d0 + NDIM;
        d0[0] += hacc[nf][0] * li0;
        d1[0] += hacc[nf][1] * li0;
        d0[8] += hacc[nf][2] * li1;
        d1[8] += hacc[nf][3] * li1;
    }
}

extern "C" void kernel_launch(void* const* d_in, const int* in_sizes, int n_in,
                              void* d_out, int out_size)
{
    const float* x  = (const float*)d_in[0];
    const float* Wq = (const float*)d_in[1];
    const float* bq = (const float*)d_in[2];
    const float* Wk = (const float*)d_in[3];
    const float* bk = (const float*)d_in[4];
    const float* Wv = (const float*)d_in[5];
    const float* bv = (const float*)d_in[6];
    const float* Wp = (const float*)d_in[7];
    const float* bp = (const float*)d_in[8];
    float* out = (float*)d_out;

    cudaFuncSetAttribute(attn_kernel,
                         cudaFuncAttributeMaxDynamicSharedMemorySize, SM_TOT * 4);

    proj_kernel<<<dim3(32, 2, 32), 256>>>(x, Wq, bq, Wk, bk, Wv, bv, Wp, bp, out);
    attn_kernel<<<dim3(NDIM / QR, BDIM), 256, SM_TOT * 4>>>(out);
}

// round 6
// speedup vs baseline: 5.5890x; 2.0096x over previous
#include <cuda_runtime.h>
#include <cuda_bf16.h>
#include <math.h>
#include <stdint.h>

#define CDIM 256
#define NDIM 4096
#define BDIM 8
#define QR   64
#define TK   64
#define NT   (NDIM / TK)   // 64

__device__ __nv_bfloat16 g_q[(size_t)BDIM * NDIM * CDIM];   // [b][n][c]
__device__ __nv_bfloat16 g_k[(size_t)BDIM * NDIM * CDIM];   // [b][n][c]
__device__ __nv_bfloat16 g_v[(size_t)BDIM * NDIM * CDIM];   // [b][c][n] (transposed)

// ---- attn smem byte offsets (tile swizzle: 16B chunk ^= row&7) ----
#define SQ_OFF 0u          // 64 x 256 bf16 (row 512B, 32 chunks)
#define SK_OFF 32768u      // 2 x (64 x 256 bf16)
#define SV_OFF 98304u      // 2 x (256 x 64 bf16) (row 128B, 8 chunks)
#define SP_OFF 163840u     // 64 x 64 bf16 (row 128B)
#define SL_OFF 172032u     // 2 x 64 f32
#define SM_BYTES 172544u

// ---------------- helpers ----------------
__device__ __forceinline__ uint32_t smem_u32(const void* p) {
    uint32_t a;
    asm("{ .reg .u64 t; cvta.to.shared.u64 t, %1; cvt.u32.u64 %0, t; }" : "=r"(a) : "l"(p));
    return a;
}
__device__ __forceinline__ float ex2(float x) {
    float y; asm("ex2.approx.f32 %0, %1;" : "=f"(y) : "f"(x)); return y;
}
__device__ __forceinline__ uint32_t bf2(float lo, float hi) {
    __nv_bfloat162 h = __float22bfloat162_rn(make_float2(lo, hi));
    return *(uint32_t*)&h;
}
__device__ __forceinline__ void cp16(uint32_t saddr, const void* gaddr) {
    asm volatile("cp.async.cg.shared.global [%0], [%1], 16;" :: "r"(saddr), "l"(gaddr));
}
__device__ __forceinline__ void cp_commit() {
    asm volatile("cp.async.commit_group;" ::: "memory");
}
template <int N>
__device__ __forceinline__ void cp_wait() {
    asm volatile("cp.async.wait_group %0;" :: "n"(N) : "memory");
}
__device__ __forceinline__ void ldm4(uint32_t* r, uint32_t addr) {
    asm volatile("ldmatrix.sync.aligned.m8n8.x4.shared.b16 {%0,%1,%2,%3}, [%4];"
        : "=r"(r[0]), "=r"(r[1]), "=r"(r[2]), "=r"(r[3]) : "r"(addr));
}
__device__ __forceinline__ void mma16(float* d, const uint32_t* a, uint32_t b0, uint32_t b1) {
    asm volatile("mma.sync.aligned.m16n8k16.row.col.f32.bf16.bf16.f32 "
        "{%0,%1,%2,%3}, {%4,%5,%6,%7}, {%8,%9}, {%0,%1,%2,%3};"
        : "+f"(d[0]), "+f"(d[1]), "+f"(d[2]), "+f"(d[3])
        : "r"(a[0]), "r"(a[1]), "r"(a[2]), "r"(a[3]), "r"(b0), "r"(b1));
}

// ---------------- projection (fp32 CUDA cores; q/k/v out as bf16) ----------
__global__ __launch_bounds__(256) void proj_kernel(
    const float* __restrict__ x,
    const float* __restrict__ Wq, const float* __restrict__ bq,
    const float* __restrict__ Wk, const float* __restrict__ bk,
    const float* __restrict__ Wv, const float* __restrict__ bv,
    const float* __restrict__ Wp, const float* __restrict__ bp,
    float* __restrict__ out)
{
    __shared__ float sX[16 * 128];
    __shared__ float sW[16 * 128];
    const int p  = blockIdx.z & 3;
    const int b  = blockIdx.z >> 2;
    const int n0 = blockIdx.x * 128;
    const int o0 = blockIdx.y * 128;
    const float* W; const float* bias;
    if (p == 0)      { W = Wq; bias = bq; }
    else if (p == 1) { W = Wk; bias = bk; }
    else if (p == 2) { W = Wv; bias = bv; }
    else             { W = Wp; bias = bp; }
    const int tid = threadIdx.x, it = tid >> 4, jt = tid & 15;

    float acc[8][8];
    #pragma unroll
    for (int r = 0; r < 8; r++)
        #pragma unroll
        for (int w = 0; w < 8; w++) acc[r][w] = 0.f;
    const float* xb = x + (size_t)b * CDIM * NDIM;

    for (int c0 = 0; c0 < CDIM; c0 += 16) {
        __syncthreads();
        #pragma unroll
        for (int q = 0; q < 2; q++) {
            int idx4 = tid + 256 * q, cc = idx4 >> 5, nn4 = idx4 & 31;
            ((float4*)sX)[cc * 32 + nn4] =
                *(const float4*)(xb + (size_t)(c0 + cc) * NDIM + n0 + nn4 * 4);
        }
        #pragma unroll
        for (int q = 0; q < 2; q++) {
            int idx4 = tid + 256 * q, oo = idx4 >> 2, cc4 = idx4 & 3;
            float4 wv = *(const float4*)(W + (size_t)(o0 + oo) * CDIM + c0 + cc4 * 4);
            sW[(cc4 * 4 + 0) * 128 + oo] = wv.x;
            sW[(cc4 * 4 + 1) * 128 + oo] = wv.y;
            sW[(cc4 * 4 + 2) * 128 + oo] = wv.z;
            sW[(cc4 * 4 + 3) * 128 + oo] = wv.w;
        }
        __syncthreads();
        #pragma unroll
        for (int cc = 0; cc < 16; cc++) {
            float4 xa  = ((const float4*)(sX + cc * 128))[it * 2];
            float4 xb4 = ((const float4*)(sX + cc * 128))[it * 2 + 1];
            float4 wa  = ((const float4*)(sW + cc * 128))[jt];
            float4 wb  = ((const float4*)(sW + cc * 128))[jt + 16];
            float xs[8] = {xa.x, xa.y, xa.z, xa.w, xb4.x, xb4.y, xb4.z, xb4.w};
            float ws[8] = {wa.x, wa.y, wa.z, wa.w, wb.x,  wb.y,  wb.z,  wb.w};
            #pragma unroll
            for (int r = 0; r < 8; r++)
                #pragma unroll
                for (int w = 0; w < 8; w++) acc[r][w] += xs[r] * ws[w];
        }
    }
    float bias_v[8];
    #pragma unroll
    for (int w = 0; w < 8; w++) {
        int o = o0 + ((w < 4) ? (4 * jt + w) : (64 + 4 * jt + (w - 4)));
        bias_v[w] = bias[o];
    }
    if (p < 2) {   // q/k: bf16 [b][n][c]
        __nv_bfloat16* dst = ((p == 0) ? g_q : g_k) + (size_t)b * NDIM * CDIM;
        #pragma unroll
        for (int r = 0; r < 8; r++) {
            int n = n0 + it * 8 + r;
            uint2 u1 = make_uint2(bf2(acc[r][0]+bias_v[0], acc[r][1]+bias_v[1]),
                                  bf2(acc[r][2]+bias_v[2], acc[r][3]+bias_v[3]));
            uint2 u2 = make_uint2(bf2(acc[r][4]+bias_v[4], acc[r][5]+bias_v[5]),
                                  bf2(acc[r][6]+bias_v[6], acc[r][7]+bias_v[7]));
            *(uint2*)(dst + (size_t)n * CDIM + o0 + 4 * jt)      = u1;
            *(uint2*)(dst + (size_t)n * CDIM + o0 + 64 + 4 * jt) = u2;
        }
    } else if (p == 2) {   // v: bf16 [b][c][n]
        __nv_bfloat16* dstb = g_v + (size_t)b * CDIM * NDIM;
        #pragma unroll
        for (int w = 0; w < 8; w++) {
            int o = o0 + ((w < 4) ? (4 * jt + w) : (64 + 4 * jt + (w - 4)));
            __nv_bfloat16* dst = dstb + (size_t)o * NDIM + n0 + it * 8;
            uint4 u;
            u.x = bf2(acc[0][w]+bias_v[w], acc[1][w]+bias_v[w]);
            u.y = bf2(acc[2][w]+bias_v[w], acc[3][w]+bias_v[w]);
            u.z = bf2(acc[4][w]+bias_v[w], acc[5][w]+bias_v[w]);
            u.w = bf2(acc[6][w]+bias_v[w], acc[7][w]+bias_v[w]);
            *(uint4*)dst = u;
        }
    } else {               // proj: fp32 [b][o][n]
        #pragma unroll
        for (int w = 0; w < 8; w++) {
            int o = o0 + ((w < 4) ? (4 * jt + w) : (64 + 4 * jt + (w - 4)));
            float* dst = out + ((size_t)b * CDIM + o) * NDIM + n0 + it * 8;
            *(float4*)(dst)     = make_float4(acc[0][w]+bias_v[w], acc[1][w]+bias_v[w],
                                              acc[2][w]+bias_v[w], acc[3][w]+bias_v[w]);
            *(float4*)(dst + 4) = make_float4(acc[4][w]+bias_v[w], acc[5][w]+bias_v[w],
                                              acc[6][w]+bias_v[w], acc[7][w]+bias_v[w]);
        }
    }
}

// ---------------- K/V tile loader (cp.async, bf16, swizzled) ---------------
__device__ __forceinline__ void load_kv(uint32_t sm0, const __nv_bfloat16* kb,
                                        const __nv_bfloat16* vb, int i, int buf, int tid)
{
    const int m0 = i * TK;
    const uint32_t sk = sm0 + SK_OFF + (uint32_t)buf * 32768u;
    const uint32_t sv = sm0 + SV_OFF + (uint32_t)buf * 32768u;
    #pragma unroll
    for (int j = 0; j < 8; j++) {          // K: 64 keys x 256 c
        int idx = tid + 256 * j, r = idx >> 5, ch = idx & 31;
        cp16(sk + (uint32_t)r * 512u + (uint32_t)((ch ^ (r & 7)) << 4),
             kb + (size_t)(m0 + r) * CDIM + ch * 8);
    }
    #pragma unroll
    for (int j = 0; j < 8; j++) {          // V^T: 256 c x 64 keys
        int idx = tid + 256 * j, r = idx >> 3, ch = idx & 7;
        cp16(sv + (uint32_t)r * 128u + (uint32_t)((ch ^ (r & 7)) << 4),
             vb + (size_t)r * NDIM + m0 + ch * 8);
    }
}

// ---------------- bf16 mma flash attention ---------------------------------
// grid (64, 8), 256 thr, 8 warps: S warp tile 16x32 (4m x 2n), PV 16x128.
__global__ __launch_bounds__(256, 1) void attn_kernel(float* __restrict__ out)
{
    extern __shared__ char smc[];
    const uint32_t sm0 = smem_u32(smc);
    const int tid = threadIdx.x, lane = tid & 31;
    const int w = tid >> 5, wm = w >> 1, wn = w & 1;
    const int g = lane >> 2, t = lane & 3;
    const int b = blockIdx.y, n0 = blockIdx.x * QR;

    const __nv_bfloat16* qb = g_q + ((size_t)b * NDIM + n0) * CDIM;
    const __nv_bfloat16* kb = g_k + (size_t)b * NDIM * CDIM;
    const __nv_bfloat16* vb = g_v + (size_t)b * CDIM * NDIM;

    // prologue: Q + tile0 in one cp.async group
    #pragma unroll
    for (int j = 0; j < 8; j++) {
        int idx = tid + 256 * j, r = idx >> 5, ch = idx & 31;
        cp16(sm0 + SQ_OFF + (uint32_t)r * 512u + (uint32_t)((ch ^ (r & 7)) << 4),
             qb + (size_t)r * CDIM + ch * 8);
    }
    load_kv(sm0, kb, vb, 0, 0, tid);
    cp_commit();

    // ldmatrix lane geometry
    const int rA  = 16 * wm + ((lane >> 3) & 1) * 8 + (lane & 7);  // A rows (Q/P)
    const int cAo = lane >> 4;                                      // k-octet select
    const int xA  = rA & 7;
    const int rB_ = ((lane >> 4) & 1) * 8 + (lane & 7);             // B row-in-16
    const int cBo = (lane >> 3) & 1;
    const int xB  = lane & 7;
    const uint32_t qA = sm0 + SQ_OFF + (uint32_t)rA * 512u;
    const uint32_t pA = sm0 + SP_OFF + (uint32_t)rA * 128u;

    float hacc[16][4];
    #pragma unroll
    for (int nf = 0; nf < 16; nf++)
        #pragma unroll
        for (int k = 0; k < 4; k++) hacc[nf][k] = 0.f;
    float lsum0 = 0.f, lsum1 = 0.f;
    const float EC = 0.0901684400555602f;    // log2(e)/16

    for (int i = 0; i < NT; i++) {
        const int buf = i & 1;
        if (i + 1 < NT) { load_kv(sm0, kb, vb, i + 1, buf ^ 1, tid); cp_commit(); cp_wait<1>(); }
        else            { cp_wait<0>(); }
        __syncthreads();

        // ---- S = Q K^T (warp tile 16 x 32) ----
        float sacc[4][4];
        #pragma unroll
        for (int f = 0; f < 4; f++)
            #pragma unroll
            for (int k = 0; k < 4; k++) sacc[f][k] = 0.f;
        const uint32_t kB0 = sm0 + SK_OFF + (uint32_t)buf * 32768u
                           + (uint32_t)(32 * wn + rB_) * 512u;
        const uint32_t kB1 = kB0 + 8192u;     // +16 key rows
        #pragma unroll
        for (int ks = 0; ks < 16; ks++) {
            uint32_t aq[4], b0[4], b1[4];
            ldm4(aq, qA + (uint32_t)(((2 * ks + cAo) ^ xA) << 4));
            uint32_t ko = (uint32_t)(((2 * ks + cBo) ^ xB) << 4);
            ldm4(b0, kB0 + ko);
            ldm4(b1, kB1 + ko);
            mma16(sacc[0], aq, b0[0], b0[1]);
            mma16(sacc[1], aq, b0[2], b0[3]);
            mma16(sacc[2], aq, b1[0], b1[1]);
            mma16(sacc[3], aq, b1[2], b1[3]);
        }

        // ---- softmax (max-free) -> sP bf16, accumulate l ----
        {
            char* p0p = smc + SP_OFF + (16 * wm + g) * 128 + 4 * t;
            char* p1p = p0p + 8 * 128;
            #pragma unroll
            for (int f = 0; f < 4; f++) {
                float e0 = ex2(sacc[f][0] * EC);
                float e1 = ex2(sacc[f][1] * EC);
                float e2 = ex2(sacc[f][2] * EC);
                float e3 = ex2(sacc[f][3] * EC);
                lsum0 += e0 + e1;
                lsum1 += e2 + e3;
                int off = ((4 * wn + f) ^ g) << 4;
                *(uint32_t*)(p0p + off) = bf2(e0, e1);
                *(uint32_t*)(p1p + off) = bf2(e2, e3);
            }
        }
        __syncthreads();

        // ---- H += P V (warp tile 16 x 128) ----
        const uint32_t vB = sm0 + SV_OFF + (uint32_t)buf * 32768u
                          + (uint32_t)(128 * wn + rB_) * 128u;
        #pragma unroll
        for (int ks = 0; ks < 4; ks++) {
            uint32_t ap[4];
            ldm4(ap, pA + (uint32_t)(((2 * ks + cAo) ^ xA) << 4));
            uint32_t vo = (uint32_t)(((2 * ks + cBo) ^ xB) << 4);
            #pragma unroll
            for (int nb = 0; nb < 8; nb++) {
                uint32_t bv[4];
                ldm4(bv, vB + (uint32_t)nb * 2048u + vo);
                mma16(hacc[2 * nb],     ap, bv[0], bv[1]);
                mma16(hacc[2 * nb + 1], ap, bv[2], bv[3]);
            }
        }
        __syncthreads();
    }

    // ---- l reduction (t lanes, then wn halves via smem) ----
    float* sl = (float*)(smc + SL_OFF);
    lsum0 += __shfl_xor_sync(0xffffffffu, lsum0, 1);
    lsum0 += __shfl_xor_sync(0xffffffffu, lsum0, 2);
    lsum1 += __shfl_xor_sync(0xffffffffu, lsum1, 1);
    lsum1 += __shfl_xor_sync(0xffffffffu, lsum1, 2);
    if (t == 0) {
        sl[wn * QR + 16 * wm + g]     = lsum0;
        sl[wn * QR + 16 * wm + 8 + g] = lsum1;
    }
    __syncthreads();
    const int r0 = 16 * wm + g;
    float li0 = 1.f / (sl[r0]     + sl[QR + r0]);
    float li1 = 1.f / (sl[r0 + 8] + sl[QR + r0 + 8]);

    // ---- epilogue: out[b][c][n] += h / l ----
    float* ob = out + (size_t)b * CDIM * NDIM + n0;
    #pragma unroll
    for (int nf = 0; nf < 16; nf++) {
        int c = wn * 128 + nf * 8 + 2 * t;
        float* d0 = ob + (size_t)c * NDIM + r0;
        float* d1 = d0 + NDIM;
        d0[0] += hacc[nf][0] * li0;
        d1[0] += hacc[nf][1] * li0;
        d0[8] += hacc[nf][2] * li1;
        d1[8] += hacc[nf][3] * li1;
    }
}

extern "C" void kernel_launch(void* const* d_in, const int* in_sizes, int n_in,
                              void* d_out, int out_size)
{
    const float* x  = (const float*)d_in[0];
    const float* Wq = (const float*)d_in[1];
    const float* bq = (const float*)d_in[2];
    const float* Wk = (const float*)d_in[3];
    const float* bk = (const float*)d_in[4];
    const float* Wv = (const float*)d_in[5];
    const float* bv = (const float*)d_in[6];
    const float* Wp = (const float*)d_in[7];
    const float* bp = (const float*)d_in[8];
    float* out = (float*)d_out;

    cudaFuncSetAttribute(attn_kernel,
                         cudaFuncAttributeMaxDynamicSharedMemorySize, SM_BYTES);

    proj_kernel<<<dim3(32, 2, 32), 256>>>(x, Wq, bq, Wk, bk, Wv, bv, Wp, bp, out);
    attn_kernel<<<dim3(NDIM / QR, BDIM), 256, SM_BYTES>>>(out);
}

// round 7
// speedup vs baseline: 6.7694x; 1.2112x over previous
#include <cuda_runtime.h>
#include <cuda_bf16.h>
#include <math.h>
#include <stdint.h>

#define CDIM 256
#define NDIM 4096
#define BDIM 8
#define QR   64
#define TK   64
#define NT   (NDIM / TK)   // 64

__device__ __nv_bfloat16 g_q[(size_t)BDIM * NDIM * CDIM];   // [b][n][c]
__device__ __nv_bfloat16 g_k[(size_t)BDIM * NDIM * CDIM];   // [b][n][c]
__device__ __nv_bfloat16 g_v[(size_t)BDIM * NDIM * CDIM];   // [b][c][n] (transposed)

// ---- attn smem byte offsets (tile swizzle: 16B chunk ^= row&7) ----
#define SQ_OFF 0u
#define SK_OFF 32768u
#define SV_OFF 98304u
#define SP_OFF 163840u
#define SL_OFF 172032u
#define SM_BYTES 172544u

// ---- proj smem float offsets ----
#define PXH 0            // 32 x 136
#define PXL 4352
#define PWH 8704         // 256 x 36
#define PWL 17920
#define PSM_FLOATS 27136
#define PSM_BYTES (PSM_FLOATS * 4)

// ---------------- helpers ----------------
__device__ __forceinline__ uint32_t smem_u32(const void* p) {
    uint32_t a;
    asm("{ .reg .u64 t; cvta.to.shared.u64 t, %1; cvt.u32.u64 %0, t; }" : "=r"(a) : "l"(p));
    return a;
}
__device__ __forceinline__ float ex2(float x) {
    float y; asm("ex2.approx.f32 %0, %1;" : "=f"(y) : "f"(x)); return y;
}
__device__ __forceinline__ float to_tf32(float x) {
    float r; asm("cvt.rna.tf32.f32 %0, %1;" : "=f"(r) : "f"(x)); return r;
}
__device__ __forceinline__ uint32_t bf2(float lo, float hi) {
    __nv_bfloat162 h = __float22bfloat162_rn(make_float2(lo, hi));
    return *(uint32_t*)&h;
}
__device__ __forceinline__ void cp16(uint32_t saddr, const void* gaddr) {
    asm volatile("cp.async.cg.shared.global [%0], [%1], 16;" :: "r"(saddr), "l"(gaddr));
}
__device__ __forceinline__ void cp_commit() {
    asm volatile("cp.async.commit_group;" ::: "memory");
}
template <int N>
__device__ __forceinline__ void cp_wait() {
    asm volatile("cp.async.wait_group %0;" :: "n"(N) : "memory");
}
__device__ __forceinline__ void ldm4(uint32_t* r, uint32_t addr) {
    asm volatile("ldmatrix.sync.aligned.m8n8.x4.shared.b16 {%0,%1,%2,%3}, [%4];"
        : "=r"(r[0]), "=r"(r[1]), "=r"(r[2]), "=r"(r[3]) : "r"(addr));
}
__device__ __forceinline__ void mma16(float* d, const uint32_t* a, uint32_t b0, uint32_t b1) {
    asm volatile("mma.sync.aligned.m16n8k16.row.col.f32.bf16.bf16.f32 "
        "{%0,%1,%2,%3}, {%4,%5,%6,%7}, {%8,%9}, {%0,%1,%2,%3};"
        : "+f"(d[0]), "+f"(d[1]), "+f"(d[2]), "+f"(d[3])
        : "r"(a[0]), "r"(a[1]), "r"(a[2]), "r"(a[3]), "r"(b0), "r"(b1));
}
__device__ __forceinline__ void mma8(float* d, float a0, float a1, float a2, float a3,
                                     float b0, float b1) {
    asm volatile("mma.sync.aligned.m16n8k8.row.col.f32.tf32.tf32.f32 "
        "{%0,%1,%2,%3}, {%4,%5,%6,%7}, {%8,%9}, {%0,%1,%2,%3};"
        : "+f"(d[0]), "+f"(d[1]), "+f"(d[2]), "+f"(d[3])
        : "r"(__float_as_uint(a0)), "r"(__float_as_uint(a1)),
          "r"(__float_as_uint(a2)), "r"(__float_as_uint(a3)),
          "r"(__float_as_uint(b0)), "r"(__float_as_uint(b1)));
}

// ---------------- tensor-core projection ------------------------------------
// grid (32 n-tiles, 4 p, 8 b), 256 thr. CTA: 256 o x 128 n, K chunks of 32.
// p<2 (q,k): A=X^T, B=W  -> D[n][o] bf16 [b][n][c]
// p=2 (v):   A=W, B=X    -> D[o][n] bf16 [b][c][n]
// p=3 (res): A=W, B=X, 2-term compensated tf32 -> fp32 out [b][c][n]
__global__ __launch_bounds__(256, 1) void proj_mma_kernel(
    const float* __restrict__ x,
    const float* __restrict__ Wq, const float* __restrict__ bq,
    const float* __restrict__ Wk, const float* __restrict__ bk,
    const float* __restrict__ Wv, const float* __restrict__ bv,
    const float* __restrict__ Wp, const float* __restrict__ bp,
    float* __restrict__ out)
{
    extern __shared__ float ps[];
    float* sXh = ps + PXH;
    float* sXl = ps + PXL;
    float* sWh = ps + PWH;
    float* sWl = ps + PWL;

    const int p  = blockIdx.y;
    const int b  = blockIdx.z;
    const int n0 = blockIdx.x * 128;
    const float* W; const float* bias;
    if (p == 0)      { W = Wq; bias = bq; }
    else if (p == 1) { W = Wk; bias = bk; }
    else if (p == 2) { W = Wv; bias = bv; }
    else             { W = Wp; bias = bp; }
    const bool do_lo = (p == 3);

    const int tid = threadIdx.x, lane = tid & 31, w = tid >> 5;
    const int g = lane >> 2, t = lane & 3;
    const int wx = w >> 1;          // o quadrant (64)
    const int wy = w & 1;           // n half (64)
    const float* xb = x + (size_t)b * CDIM * NDIM + n0;

    float4 xr[4], wr[8];
    // prologue: LDG chunk 0
    #pragma unroll
    for (int j = 0; j < 4; j++) {
        int idx = tid + 256 * j, r = idx >> 5, ch = idx & 31;
        xr[j] = *(const float4*)(xb + (size_t)r * NDIM + ch * 4);
    }
    #pragma unroll
    for (int j = 0; j < 8; j++) {
        int idx = tid + 256 * j, r = idx >> 3, ch = idx & 7;
        wr[j] = *(const float4*)(W + r * CDIM + ch * 4);
    }

    float acc[4][8][4];
    #pragma unroll
    for (int mf = 0; mf < 4; mf++)
        #pragma unroll
        for (int nf = 0; nf < 8; nf++)
            #pragma unroll
            for (int k = 0; k < 4; k++) acc[mf][nf][k] = 0.f;

    for (int kc = 0; kc < 8; kc++) {
        // STS (hi/lo split)
        #pragma unroll
        for (int j = 0; j < 4; j++) {
            int idx = tid + 256 * j, r = idx >> 5, ch = idx & 31;
            float4 v = xr[j];
            float4 h = make_float4(to_tf32(v.x), to_tf32(v.y), to_tf32(v.z), to_tf32(v.w));
            *(float4*)(sXh + r * 136 + ch * 4) = h;
            if (do_lo)
                *(float4*)(sXl + r * 136 + ch * 4) =
                    make_float4(to_tf32(v.x - h.x), to_tf32(v.y - h.y),
                                to_tf32(v.z - h.z), to_tf32(v.w - h.w));
        }
        #pragma unroll
        for (int j = 0; j < 8; j++) {
            int idx = tid + 256 * j, r = idx >> 3, ch = idx & 7;
            float4 v = wr[j];
            float4 h = make_float4(to_tf32(v.x), to_tf32(v.y), to_tf32(v.z), to_tf32(v.w));
            *(float4*)(sWh + r * 36 + ch * 4) = h;
            if (do_lo)
                *(float4*)(sWl + r * 36 + ch * 4) =
                    make_float4(to_tf32(v.x - h.x), to_tf32(v.y - h.y),
                                to_tf32(v.z - h.z), to_tf32(v.w - h.w));
        }
        __syncthreads();

        if (kc < 7) {   // prefetch next chunk during mma
            const float* xn = xb + (size_t)(kc + 1) * 32 * NDIM;
            #pragma unroll
            for (int j = 0; j < 4; j++) {
                int idx = tid + 256 * j, r = idx >> 5, ch = idx & 31;
                xr[j] = *(const float4*)(xn + (size_t)r * NDIM + ch * 4);
            }
            const float* wn = W + (kc + 1) * 32;
            #pragma unroll
            for (int j = 0; j < 8; j++) {
                int idx = tid + 256 * j, r = idx >> 3, ch = idx & 7;
                wr[j] = *(const float4*)(wn + r * CDIM + ch * 4);
            }
        }

        // ---- mma over 4 k-steps of 8 ----
        #pragma unroll
        for (int ks = 0; ks < 4; ks++) {
            const int c0i = 8 * ks + t;
            float ah[4][4], bh[8][2];
            if (p < 2) {
                const float* x0 = sXh + c0i * 136 + 64 * wy;
                const float* x4 = x0 + 4 * 136;
                #pragma unroll
                for (int mf = 0; mf < 4; mf++) {
                    ah[mf][0] = x0[16 * mf + g];
                    ah[mf][1] = x0[16 * mf + 8 + g];
                    ah[mf][2] = x4[16 * mf + g];
                    ah[mf][3] = x4[16 * mf + 8 + g];
                }
                #pragma unroll
                for (int nf = 0; nf < 8; nf++) {
                    const float* wrow = sWh + (64 * wx + 8 * nf + g) * 36;
                    bh[nf][0] = wrow[c0i];
                    bh[nf][1] = wrow[c0i + 4];
                }
                #pragma unroll
                for (int mf = 0; mf < 4; mf++)
                    #pragma unroll
                    for (int nf = 0; nf < 8; nf++)
                        mma8(acc[mf][nf], ah[mf][0], ah[mf][1], ah[mf][2], ah[mf][3],
                             bh[nf][0], bh[nf][1]);
            } else {
                #pragma unroll
                for (int mf = 0; mf < 4; mf++) {
                    const float* w0 = sWh + (64 * wx + 16 * mf + g) * 36;
                    const float* w8 = w0 + 8 * 36;
                    ah[mf][0] = w0[c0i];
                    ah[mf][1] = w8[c0i];
                    ah[mf][2] = w0[c0i + 4];
                    ah[mf][3] = w8[c0i + 4];
                }
                const float* x0 = sXh + c0i * 136 + 64 * wy;
                const float* x4 = x0 + 4 * 136;
                #pragma unroll
                for (int nf = 0; nf < 8; nf++) {
                    bh[nf][0] = x0[8 * nf + g];
                    bh[nf][1] = x4[8 * nf + g];
                }
                #pragma unroll
                for (int mf = 0; mf < 4; mf++)
                    #pragma unroll
                    for (int nf = 0; nf < 8; nf++)
                        mma8(acc[mf][nf], ah[mf][0], ah[mf][1], ah[mf][2], ah[mf][3],
                             bh[nf][0], bh[nf][1]);
                if (do_lo) {
                    float al[4][4], bl[8][2];
                    #pragma unroll
                    for (int mf = 0; mf < 4; mf++) {
                        const float* w0 = sWl + (64 * wx + 16 * mf + g) * 36;
                        const float* w8 = w0 + 8 * 36;
                        al[mf][0] = w0[c0i];
                        al[mf][1] = w8[c0i];
                        al[mf][2] = w0[c0i + 4];
                        al[mf][3] = w8[c0i + 4];
                    }
                    const float* l0 = sXl + c0i * 136 + 64 * wy;
                    const float* l4 = l0 + 4 * 136;
                    #pragma unroll
                    for (int nf = 0; nf < 8; nf++) {
                        bl[nf][0] = l0[8 * nf + g];
                        bl[nf][1] = l4[8 * nf + g];
                    }
                    #pragma unroll
                    for (int mf = 0; mf < 4; mf++)
                        #pragma unroll
                        for (int nf = 0; nf < 8; nf++) {
                            mma8(acc[mf][nf], ah[mf][0], ah[mf][1], ah[mf][2], ah[mf][3],
                                 bl[nf][0], bl[nf][1]);
                            mma8(acc[mf][nf], al[mf][0], al[mf][1], al[mf][2], al[mf][3],
                                 bh[nf][0], bh[nf][1]);
                        }
                }
            }
        }
        __syncthreads();
    }

    // ---- epilogue ----
    if (p < 2) {
        __nv_bfloat16* dst = ((p == 0) ? g_q : g_k) + (size_t)b * NDIM * CDIM;
        #pragma unroll
        for (int mf = 0; mf < 4; mf++) {
            int n = n0 + 64 * wy + 16 * mf + g;
            #pragma unroll
            for (int nf = 0; nf < 8; nf++) {
                int o = 64 * wx + 8 * nf + 2 * t;
                float2 bs = *(const float2*)(bias + o);
                *(uint32_t*)(dst + (size_t)n * CDIM + o) =
                    bf2(acc[mf][nf][0] + bs.x, acc[mf][nf][1] + bs.y);
                *(uint32_t*)(dst + (size_t)(n + 8) * CDIM + o) =
                    bf2(acc[mf][nf][2] + bs.x, acc[mf][nf][3] + bs.y);
            }
        }
    } else if (p == 2) {
        __nv_bfloat16* dst = g_v + (size_t)b * CDIM * NDIM;
        #pragma unroll
        for (int mf = 0; mf < 4; mf++) {
            int o = 64 * wx + 16 * mf + g;
            float b0 = bias[o], b8 = bias[o + 8];
            #pragma unroll
            for (int nf = 0; nf < 8; nf++) {
                int n = n0 + 64 * wy + 8 * nf + 2 * t;
                *(uint32_t*)(dst + (size_t)o * NDIM + n) =
                    bf2(acc[mf][nf][0] + b0, acc[mf][nf][1] + b0);
                *(uint32_t*)(dst + (size_t)(o + 8) * NDIM + n) =
                    bf2(acc[mf][nf][2] + b8, acc[mf][nf][3] + b8);
            }
        }
    } else {
        float* dst = out + (size_t)b * CDIM * NDIM;
        #pragma unroll
        for (int mf = 0; mf < 4; mf++) {
            int o = 64 * wx + 16 * mf + g;
            float b0 = bias[o], b8 = bias[o + 8];
            #pragma unroll
            for (int nf = 0; nf < 8; nf++) {
                int n = n0 + 64 * wy + 8 * nf + 2 * t;
                *(float2*)(dst + (size_t)o * NDIM + n) =
                    make_float2(acc[mf][nf][0] + b0, acc[mf][nf][1] + b0);
                *(float2*)(dst + (size_t)(o + 8) * NDIM + n) =
                    make_float2(acc[mf][nf][2] + b8, acc[mf][nf][3] + b8);
            }
        }
    }
}

// ---------------- K/V tile loader (cp.async, bf16, swizzled) ---------------
__device__ __forceinline__ void load_kv(uint32_t sm0, const __nv_bfloat16* kb,
                                        const __nv_bfloat16* vb, int i, int buf, int tid)
{
    const int m0 = i * TK;
    const uint32_t sk = sm0 + SK_OFF + (uint32_t)buf * 32768u;
    const uint32_t sv = sm0 + SV_OFF + (uint32_t)buf * 32768u;
    #pragma unroll
    for (int j = 0; j < 8; j++) {
        int idx = tid + 256 * j, r = idx >> 5, ch = idx & 31;
        cp16(sk + (uint32_t)r * 512u + (uint32_t)((ch ^ (r & 7)) << 4),
             kb + (size_t)(m0 + r) * CDIM + ch * 8);
    }
    #pragma unroll
    for (int j = 0; j < 8; j++) {
        int idx = tid + 256 * j, r = idx >> 3, ch = idx & 7;
        cp16(sv + (uint32_t)r * 128u + (uint32_t)((ch ^ (r & 7)) << 4),
             vb + (size_t)r * NDIM + m0 + ch * 8);
    }
}

// ---------------- bf16 mma flash attention (unchanged from R6) -------------
__global__ __launch_bounds__(256, 1) void attn_kernel(float* __restrict__ out)
{
    extern __shared__ char smc[];
    const uint32_t sm0 = smem_u32(smc);
    const int tid = threadIdx.x, lane = tid & 31;
    const int w = tid >> 5, wm = w >> 1, wn = w & 1;
    const int g = lane >> 2, t = lane & 3;
    const int b = blockIdx.y, n0 = blockIdx.x * QR;

    const __nv_bfloat16* qb = g_q + ((size_t)b * NDIM + n0) * CDIM;
    const __nv_bfloat16* kb = g_k + (size_t)b * NDIM * CDIM;
    const __nv_bfloat16* vb = g_v + (size_t)b * CDIM * NDIM;

    #pragma unroll
    for (int j = 0; j < 8; j++) {
        int idx = tid + 256 * j, r = idx >> 5, ch = idx & 31;
        cp16(sm0 + SQ_OFF + (uint32_t)r * 512u + (uint32_t)((ch ^ (r & 7)) << 4),
             qb + (size_t)r * CDIM + ch * 8);
    }
    load_kv(sm0, kb, vb, 0, 0, tid);
    cp_commit();

    const int rA  = 16 * wm + ((lane >> 3) & 1) * 8 + (lane & 7);
    const int cAo = lane >> 4;
    const int xA  = rA & 7;
    const int rB_ = ((lane >> 4) & 1) * 8 + (lane & 7);
    const int cBo = (lane >> 3) & 1;
    const int xB  = lane & 7;
    const uint32_t qA = sm0 + SQ_OFF + (uint32_t)rA * 512u;
    const uint32_t pA = sm0 + SP_OFF + (uint32_t)rA * 128u;

    float hacc[16][4];
    #pragma unroll
    for (int nf = 0; nf < 16; nf++)
        #pragma unroll
        for (int k = 0; k < 4; k++) hacc[nf][k] = 0.f;
    float lsum0 = 0.f, lsum1 = 0.f;
    const float EC = 0.0901684400555602f;

    for (int i = 0; i < NT; i++) {
        const int buf = i & 1;
        if (i + 1 < NT) { load_kv(sm0, kb, vb, i + 1, buf ^ 1, tid); cp_commit(); cp_wait<1>(); }
        else            { cp_wait<0>(); }
        __syncthreads();

        float sacc[4][4];
        #pragma unroll
        for (int f = 0; f < 4; f++)
            #pragma unroll
            for (int k = 0; k < 4; k++) sacc[f][k] = 0.f;
        const uint32_t kB0 = sm0 + SK_OFF + (uint32_t)buf * 32768u
                           + (uint32_t)(32 * wn + rB_) * 512u;
        const uint32_t kB1 = kB0 + 8192u;
        #pragma unroll
        for (int ks = 0; ks < 16; ks++) {
            uint32_t aq[4], b0[4], b1[4];
            ldm4(aq, qA + (uint32_t)(((2 * ks + cAo) ^ xA) << 4));
            uint32_t ko = (uint32_t)(((2 * ks + cBo) ^ xB) << 4);
            ldm4(b0, kB0 + ko);
            ldm4(b1, kB1 + ko);
            mma16(sacc[0], aq, b0[0], b0[1]);
            mma16(sacc[1], aq, b0[2], b0[3]);
            mma16(sacc[2], aq, b1[0], b1[1]);
            mma16(sacc[3], aq, b1[2], b1[3]);
        }

        {
            char* p0p = smc + SP_OFF + (16 * wm + g) * 128 + 4 * t;
            char* p1p = p0p + 8 * 128;
            #pragma unroll
            for (int f = 0; f < 4; f++) {
                float e0 = ex2(sacc[f][0] * EC);
                float e1 = ex2(sacc[f][1] * EC);
                float e2 = ex2(sacc[f][2] * EC);
                float e3 = ex2(sacc[f][3] * EC);
                lsum0 += e0 + e1;
                lsum1 += e2 + e3;
                int off = ((4 * wn + f) ^ g) << 4;
                *(uint32_t*)(p0p + off) = bf2(e0, e1);
                *(uint32_t*)(p1p + off) = bf2(e2, e3);
            }
        }
        __syncthreads();

        const uint32_t vB = sm0 + SV_OFF + (uint32_t)buf * 32768u
                          + (uint32_t)(128 * wn + rB_) * 128u;
        #pragma unroll
        for (int ks = 0; ks < 4; ks++) {
            uint32_t ap[4];
            ldm4(ap, pA + (uint32_t)(((2 * ks + cAo) ^ xA) << 4));
            uint32_t vo = (uint32_t)(((2 * ks + cBo) ^ xB) << 4);
            #pragma unroll
            for (int nb = 0; nb < 8; nb++) {
                uint32_t bv[4];
                ldm4(bv, vB + (uint32_t)nb * 2048u + vo);
                mma16(hacc[2 * nb],     ap, bv[0], bv[1]);
                mma16(hacc[2 * nb + 1], ap, bv[2], bv[3]);
            }
        }
        __syncthreads();
    }

    float* sl = (float*)(smc + SL_OFF);
    lsum0 += __shfl_xor_sync(0xffffffffu, lsum0, 1);
    lsum0 += __shfl_xor_sync(0xffffffffu, lsum0, 2);
    lsum1 += __shfl_xor_sync(0xffffffffu, lsum1, 1);
    lsum1 += __shfl_xor_sync(0xffffffffu, lsum1, 2);
    if (t == 0) {
        sl[wn * QR + 16 * wm + g]     = lsum0;
        sl[wn * QR + 16 * wm + 8 + g] = lsum1;
    }
    __syncthreads();
    const int r0 = 16 * wm + g;
    float li0 = 1.f / (sl[r0]     + sl[QR + r0]);
    float li1 = 1.f / (sl[r0 + 8] + sl[QR + r0 + 8]);

    float* ob = out + (size_t)b * CDIM * NDIM + n0;
    #pragma unroll
    for (int nf = 0; nf < 16; nf++) {
        int c = wn * 128 + nf * 8 + 2 * t;
        float* d0 = ob + (size_t)c * NDIM + r0;
        float* d1 = d0 + NDIM;
        d0[0] += hacc[nf][0] * li0;
        d1[0] += hacc[nf][1] * li0;
        d0[8] += hacc[nf][2] * li1;
        d1[8] += hacc[nf][3] * li1;
    }
}

extern "C" void kernel_launch(void* const* d_in, const int* in_sizes, int n_in,
                              void* d_out, int out_size)
{
    const float* x  = (const float*)d_in[0];
    const float* Wq = (const float*)d_in[1];
    const float* bq = (const float*)d_in[2];
    const float* Wk = (const float*)d_in[3];
    const float* bk = (const float*)d_in[4];
    const float* Wv = (const float*)d_in[5];
    const float* bv = (const float*)d_in[6];
    const float* Wp = (const float*)d_in[7];
    const float* bp = (const float*)d_in[8];
    float* out = (float*)d_out;

    cudaFuncSetAttribute(proj_mma_kernel,
                         cudaFuncAttributeMaxDynamicSharedMemorySize, PSM_BYTES);
    cudaFuncSetAttribute(attn_kernel,
                         cudaFuncAttributeMaxDynamicSharedMemorySize, SM_BYTES);

    proj_mma_kernel<<<dim3(32, 4, 8), 256, PSM_BYTES>>>(
        x, Wq, bq, Wk, bk, Wv, bv, Wp, bp, out);
    attn_kernel<<<dim3(NDIM / QR, BDIM), 256, SM_BYTES>>>(out);
}

// round 9
// speedup vs baseline: 8.2711x; 1.2218x over previous
#include <cuda_runtime.h>
#include <cuda_bf16.h>
#include <math.h>
#include <stdint.h>

#define CDIM 256
#define NDIM 4096
#define BDIM 8
#define QR   128
#define TK   64
#define NT   (NDIM / TK)   // 64

__device__ __nv_bfloat16 g_q[(size_t)BDIM * NDIM * CDIM];   // [b][n][c]
__device__ __nv_bfloat16 g_k[(size_t)BDIM * NDIM * CDIM];   // [b][n][c]
__device__ __nv_bfloat16 g_v[(size_t)BDIM * NDIM * CDIM];   // [b][c][n] (transposed)

// ---- attn smem byte offsets (tile swizzle: 16B chunk ^= row&7) ----
#define SQ_OFF 0u          // 128 x 256 bf16 (row 512B, 32 chunks) = 64KB
#define SK_OFF 65536u      // 2 x (64 x 256 bf16) = 64KB
#define SV_OFF 131072u     // 2 x (256 x 64 bf16) = 64KB
#define SP_OFF 196608u     // 128 x 64 bf16 (row 128B) = 16KB
#define SL_OFF 212992u     // 2 x 128 f32 = 1KB
#define SM_BYTES 214016u

// ---- proj smem float offsets ----
#define PXH 0            // 32 x 136
#define PXL 4352
#define PWH 8704         // 256 x 36
#define PWL 17920
#define PSM_FLOATS 27136
#define PSM_BYTES (PSM_FLOATS * 4)

// ---------------- helpers ----------------
__device__ __forceinline__ uint32_t smem_u32(const void* p) {
    uint32_t a;
    asm("{ .reg .u64 t; cvta.to.shared.u64 t, %1; cvt.u32.u64 %0, t; }" : "=r"(a) : "l"(p));
    return a;
}
__device__ __forceinline__ float ex2(float x) {
    float y; asm("ex2.approx.f32 %0, %1;" : "=f"(y) : "f"(x)); return y;
}
__device__ __forceinline__ float to_tf32(float x) {
    float r; asm("cvt.rna.tf32.f32 %0, %1;" : "=f"(r) : "f"(x)); return r;
}
__device__ __forceinline__ uint32_t bf2(float lo, float hi) {
    __nv_bfloat162 h = __float22bfloat162_rn(make_float2(lo, hi));
    return *(uint32_t*)&h;
}
__device__ __forceinline__ void cp16(uint32_t saddr, const void* gaddr) {
    asm volatile("cp.async.cg.shared.global [%0], [%1], 16;" :: "r"(saddr), "l"(gaddr));
}
__device__ __forceinline__ void cp_commit() {
    asm volatile("cp.async.commit_group;" ::: "memory");
}
template <int N>
__device__ __forceinline__ void cp_wait() {
    asm volatile("cp.async.wait_group %0;" :: "n"(N) : "memory");
}
__device__ __forceinline__ void ldm4(uint32_t* r, uint32_t addr) {
    asm volatile("ldmatrix.sync.aligned.m8n8.x4.shared.b16 {%0,%1,%2,%3}, [%4];"
        : "=r"(r[0]), "=r"(r[1]), "=r"(r[2]), "=r"(r[3]) : "r"(addr));
}
__device__ __forceinline__ void mma16(float* d, const uint32_t* a, uint32_t b0, uint32_t b1) {
    asm volatile("mma.sync.aligned.m16n8k16.row.col.f32.bf16.bf16.f32 "
        "{%0,%1,%2,%3}, {%4,%5,%6,%7}, {%8,%9}, {%0,%1,%2,%3};"
        : "+f"(d[0]), "+f"(d[1]), "+f"(d[2]), "+f"(d[3])
        : "r"(a[0]), "r"(a[1]), "r"(a[2]), "r"(a[3]), "r"(b0), "r"(b1));
}
__device__ __forceinline__ void mma8(float* d, float a0, float a1, float a2, float a3,
                                     float b0, float b1) {
    asm volatile("mma.sync.aligned.m16n8k8.row.col.f32.tf32.tf32.f32 "
        "{%0,%1,%2,%3}, {%4,%5,%6,%7}, {%8,%9}, {%0,%1,%2,%3};"
        : "+f"(d[0]), "+f"(d[1]), "+f"(d[2]), "+f"(d[3])
        : "r"(__float_as_uint(a0)), "r"(__float_as_uint(a1)),
          "r"(__float_as_uint(a2)), "r"(__float_as_uint(a3)),
          "r"(__float_as_uint(b0)), "r"(__float_as_uint(b1)));
}

// ---------------- tensor-core projection (unchanged from R7) ---------------
__global__ __launch_bounds__(256, 1) void proj_mma_kernel(
    const float* __restrict__ x,
    const float* __restrict__ Wq, const float* __restrict__ bq,
    const float* __restrict__ Wk, const float* __restrict__ bk,
    const float* __restrict__ Wv, const float* __restrict__ bv,
    const float* __restrict__ Wp, const float* __restrict__ bp,
    float* __restrict__ out)
{
    extern __shared__ float ps[];
    float* sXh = ps + PXH;
    float* sXl = ps + PXL;
    float* sWh = ps + PWH;
    float* sWl = ps + PWL;

    const int p  = blockIdx.y;
    const int b  = blockIdx.z;
    const int n0 = blockIdx.x * 128;
    const float* W; const float* bias;
    if (p == 0)      { W = Wq; bias = bq; }
    else if (p == 1) { W = Wk; bias = bk; }
    else if (p == 2) { W = Wv; bias = bv; }
    else             { W = Wp; bias = bp; }
    const bool do_lo = (p == 3);

    const int tid = threadIdx.x, lane = tid & 31, w = tid >> 5;
    const int g = lane >> 2, t = lane & 3;
    const int wx = w >> 1;
    const int wy = w & 1;
    const float* xb = x + (size_t)b * CDIM * NDIM + n0;

    float4 xr[4], wr[8];
    #pragma unroll
    for (int j = 0; j < 4; j++) {
        int idx = tid + 256 * j, r = idx >> 5, ch = idx & 31;
        xr[j] = *(const float4*)(xb + (size_t)r * NDIM + ch * 4);
    }
    #pragma unroll
    for (int j = 0; j < 8; j++) {
        int idx = tid + 256 * j, r = idx >> 3, ch = idx & 7;
        wr[j] = *(const float4*)(W + r * CDIM + ch * 4);
    }

    float acc[4][8][4];
    #pragma unroll
    for (int mf = 0; mf < 4; mf++)
        #pragma unroll
        for (int nf = 0; nf < 8; nf++)
            #pragma unroll
            for (int k = 0; k < 4; k++) acc[mf][nf][k] = 0.f;

    for (int kc = 0; kc < 8; kc++) {
        #pragma unroll
        for (int j = 0; j < 4; j++) {
            int idx = tid + 256 * j, r = idx >> 5, ch = idx & 31;
            float4 v = xr[j];
            float4 h = make_float4(to_tf32(v.x), to_tf32(v.y), to_tf32(v.z), to_tf32(v.w));
            *(float4*)(sXh + r * 136 + ch * 4) = h;
            if (do_lo)
                *(float4*)(sXl + r * 136 + ch * 4) =
                    make_float4(to_tf32(v.x - h.x), to_tf32(v.y - h.y),
                                to_tf32(v.z - h.z), to_tf32(v.w - h.w));
        }
        #pragma unroll
        for (int j = 0; j < 8; j++) {
            int idx = tid + 256 * j, r = idx >> 3, ch = idx & 7;
            float4 v = wr[j];
            float4 h = make_float4(to_tf32(v.x), to_tf32(v.y), to_tf32(v.z), to_tf32(v.w));
            *(float4*)(sWh + r * 36 + ch * 4) = h;
            if (do_lo)
                *(float4*)(sWl + r * 36 + ch * 4) =
                    make_float4(to_tf32(v.x - h.x), to_tf32(v.y - h.y),
                                to_tf32(v.z - h.z), to_tf32(v.w - h.w));
        }
        __syncthreads();

        if (kc < 7) {
            const float* xn = xb + (size_t)(kc + 1) * 32 * NDIM;
            #pragma unroll
            for (int j = 0; j < 4; j++) {
                int idx = tid + 256 * j, r = idx >> 5, ch = idx & 31;
                xr[j] = *(const float4*)(xn + (size_t)r * NDIM + ch * 4);
            }
            const float* wn = W + (kc + 1) * 32;
            #pragma unroll
            for (int j = 0; j < 8; j++) {
                int idx = tid + 256 * j, r = idx >> 3, ch = idx & 7;
                wr[j] = *(const float4*)(wn + r * CDIM + ch * 4);
            }
        }

        #pragma unroll
        for (int ks = 0; ks < 4; ks++) {
            const int c0i = 8 * ks + t;
            float ah[4][4], bh[8][2];
            if (p < 2) {
                const float* x0 = sXh + c0i * 136 + 64 * wy;
                const float* x4 = x0 + 4 * 136;
                #pragma unroll
                for (int mf = 0; mf < 4; mf++) {
                    ah[mf][0] = x0[16 * mf + g];
                    ah[mf][1] = x0[16 * mf + 8 + g];
                    ah[mf][2] = x4[16 * mf + g];
                    ah[mf][3] = x4[16 * mf + 8 + g];
                }
                #pragma unroll
                for (int nf = 0; nf < 8; nf++) {
                    const float* wrow = sWh + (64 * wx + 8 * nf + g) * 36;
                    bh[nf][0] = wrow[c0i];
                    bh[nf][1] = wrow[c0i + 4];
                }
                #pragma unroll
                for (int mf = 0; mf < 4; mf++)
                    #pragma unroll
                    for (int nf = 0; nf < 8; nf++)
                        mma8(acc[mf][nf], ah[mf][0], ah[mf][1], ah[mf][2], ah[mf][3],
                             bh[nf][0], bh[nf][1]);
            } else {
                #pragma unroll
                for (int mf = 0; mf < 4; mf++) {
                    const float* w0 = sWh + (64 * wx + 16 * mf + g) * 36;
                    const float* w8 = w0 + 8 * 36;
                    ah[mf][0] = w0[c0i];
                    ah[mf][1] = w8[c0i];
                    ah[mf][2] = w0[c0i + 4];
                    ah[mf][3] = w8[c0i + 4];
                }
                const float* x0 = sXh + c0i * 136 + 64 * wy;
                const float* x4 = x0 + 4 * 136;
                #pragma unroll
                for (int nf = 0; nf < 8; nf++) {
                    bh[nf][0] = x0[8 * nf + g];
                    bh[nf][1] = x4[8 * nf + g];
                }
                #pragma unroll
                for (int mf = 0; mf < 4; mf++)
                    #pragma unroll
                    for (int nf = 0; nf < 8; nf++)
                        mma8(acc[mf][nf], ah[mf][0], ah[mf][1], ah[mf][2], ah[mf][3],
                             bh[nf][0], bh[nf][1]);
                if (do_lo) {
                    float al[4][4], bl[8][2];
                    #pragma unroll
                    for (int mf = 0; mf < 4; mf++) {
                        const float* w0 = sWl + (64 * wx + 16 * mf + g) * 36;
                        const float* w8 = w0 + 8 * 36;
                        al[mf][0] = w0[c0i];
                        al[mf][1] = w8[c0i];
                        al[mf][2] = w0[c0i + 4];
                        al[mf][3] = w8[c0i + 4];
                    }
                    const float* l0 = sXl + c0i * 136 + 64 * wy;
                    const float* l4 = l0 + 4 * 136;
                    #pragma unroll
                    for (int nf = 0; nf < 8; nf++) {
                        bl[nf][0] = l0[8 * nf + g];
                        bl[nf][1] = l4[8 * nf + g];
                    }
                    #pragma unroll
                    for (int mf = 0; mf < 4; mf++)
                        #pragma unroll
                        for (int nf = 0; nf < 8; nf++) {
                            mma8(acc[mf][nf], ah[mf][0], ah[mf][1], ah[mf][2], ah[mf][3],
                                 bl[nf][0], bl[nf][1]);
                            mma8(acc[mf][nf], al[mf][0], al[mf][1], al[mf][2], al[mf][3],
                                 bh[nf][0], bh[nf][1]);
                        }
                }
            }
        }
        __syncthreads();
    }

    if (p < 2) {
        __nv_bfloat16* dst = ((p == 0) ? g_q : g_k) + (size_t)b * NDIM * CDIM;
        #pragma unroll
        for (int mf = 0; mf < 4; mf++) {
            int n = n0 + 64 * wy + 16 * mf + g;
            #pragma unroll
            for (int nf = 0; nf < 8; nf++) {
                int o = 64 * wx + 8 * nf + 2 * t;
                float2 bs = *(const float2*)(bias + o);
                *(uint32_t*)(dst + (size_t)n * CDIM + o) =
                    bf2(acc[mf][nf][0] + bs.x, acc[mf][nf][1] + bs.y);
                *(uint32_t*)(dst + (size_t)(n + 8) * CDIM + o) =
                    bf2(acc[mf][nf][2] + bs.x, acc[mf][nf][3] + bs.y);
            }
        }
    } else if (p == 2) {
        __nv_bfloat16* dst = g_v + (size_t)b * CDIM * NDIM;
        #pragma unroll
        for (int mf = 0; mf < 4; mf++) {
            int o = 64 * wx + 16 * mf + g;
            float b0 = bias[o], b8 = bias[o + 8];
            #pragma unroll
            for (int nf = 0; nf < 8; nf++) {
                int n = n0 + 64 * wy + 8 * nf + 2 * t;
                *(uint32_t*)(dst + (size_t)o * NDIM + n) =
                    bf2(acc[mf][nf][0] + b0, acc[mf][nf][1] + b0);
                *(uint32_t*)(dst + (size_t)(o + 8) * NDIM + n) =
                    bf2(acc[mf][nf][2] + b8, acc[mf][nf][3] + b8);
            }
        }
    } else {
        float* dst = out + (size_t)b * CDIM * NDIM;
        #pragma unroll
        for (int mf = 0; mf < 4; mf++) {
            int o = 64 * wx + 16 * mf + g;
            float b0 = bias[o], b8 = bias[o + 8];
            #pragma unroll
            for (int nf = 0; nf < 8; nf++) {
                int n = n0 + 64 * wy + 8 * nf + 2 * t;
                *(float2*)(dst + (size_t)o * NDIM + n) =
                    make_float2(acc[mf][nf][0] + b0, acc[mf][nf][1] + b0);
                *(float2*)(dst + (size_t)(o + 8) * NDIM + n) =
                    make_float2(acc[mf][nf][2] + b8, acc[mf][nf][3] + b8);
            }
        }
    }
}

// ---------------- K/V tile loader (cp.async, bf16, swizzled) ---------------
__device__ __forceinline__ void load_kv(uint32_t sm0, const __nv_bfloat16* kb,
                                        const __nv_bfloat16* vb, int i, int buf, int tid)
{
    const int m0 = i * TK;
    const uint32_t sk = sm0 + SK_OFF + (uint32_t)buf * 32768u;
    const uint32_t sv = sm0 + SV_OFF + (uint32_t)buf * 32768u;
    #pragma unroll
    for (int j = 0; j < 8; j++) {          // K: 64 keys x 256 c
        int idx = tid + 256 * j, r = idx >> 5, ch = idx & 31;
        cp16(sk + (uint32_t)r * 512u + (uint32_t)((ch ^ (r & 7)) << 4),
             kb + (size_t)(m0 + r) * CDIM + ch * 8);
    }
    #pragma unroll
    for (int j = 0; j < 8; j++) {          // V^T: 256 c x 64 keys
        int idx = tid + 256 * j, r = idx >> 3, ch = idx & 7;
        cp16(sv + (uint32_t)r * 128u + (uint32_t)((ch ^ (r & 7)) << 4),
             vb + (size_t)r * NDIM + m0 + ch * 8);
    }
}

// ---------------- bf16 mma flash attention, QR=128 --------------------------
// grid (32, 8), 256 thr, 8 warps (wm 0..3 = 32 q-rows, wn 0..1).
// S warp tile 32x32 (wn = 32-key half); PV warp tile 32x128 (wn = 128-ch half).
__global__ __launch_bounds__(256, 1) void attn_kernel(float* __restrict__ out)
{
    extern __shared__ char smc[];
    const uint32_t sm0 = smem_u32(smc);
    const int tid = threadIdx.x, lane = tid & 31;
    const int w = tid >> 5, wm = w >> 1, wn = w & 1;
    const int g = lane >> 2, t = lane & 3;
    const int b = blockIdx.y, n0 = blockIdx.x * QR;

    const __nv_bfloat16* qb = g_q + ((size_t)b * NDIM + n0) * CDIM;
    const __nv_bfloat16* kb = g_k + (size_t)b * NDIM * CDIM;
    const __nv_bfloat16* vb = g_v + (size_t)b * CDIM * NDIM;

    // prologue: Q (128x256) + tile0 in one cp.async group
    #pragma unroll
    for (int j = 0; j < 16; j++) {
        int idx = tid + 256 * j, r = idx >> 5, ch = idx & 31;
        cp16(sm0 + SQ_OFF + (uint32_t)r * 512u + (uint32_t)((ch ^ (r & 7)) << 4),
             qb + (size_t)r * CDIM + ch * 8);
    }
    load_kv(sm0, kb, vb, 0, 0, tid);
    cp_commit();

    // ldmatrix lane geometry
    const int rA  = ((lane >> 3) & 1) * 8 + (lane & 7);   // A row-in-16
    const int cAo = lane >> 4;
    const int rB_ = ((lane >> 4) & 1) * 8 + (lane & 7);   // B row-in-16
    const int cBo = (lane >> 3) & 1;
    const int xs  = lane & 7;                             // swizzle XOR
    const uint32_t qA0 = sm0 + SQ_OFF + (uint32_t)(32 * wm + rA) * 512u;
    const uint32_t qA1 = qA0 + 8192u;                     // +16 rows
    const uint32_t pA0 = sm0 + SP_OFF + (uint32_t)(32 * wm + rA) * 128u;
    const uint32_t pA1 = pA0 + 2048u;                     // +16 rows

    float hacc[2][16][4];
    #pragma unroll
    for (int mf = 0; mf < 2; mf++)
        #pragma unroll
        for (int nf = 0; nf < 16; nf++)
            #pragma unroll
            for (int k = 0; k < 4; k++) hacc[mf][nf][k] = 0.f;
    float lsum[2][2] = {{0.f, 0.f}, {0.f, 0.f}};
    const float EC = 0.0901684400555602f;    // log2(e)/16

    for (int i = 0; i < NT; i++) {
        const int buf = i & 1;
        if (i + 1 < NT) { load_kv(sm0, kb, vb, i + 1, buf ^ 1, tid); cp_commit(); cp_wait<1>(); }
        else            { cp_wait<0>(); }
        __syncthreads();

        // ---- S = Q K^T (warp tile 32 x 32; wn = key half) ----
        float sacc[2][4][4];
        #pragma unroll
        for (int mf = 0; mf < 2; mf++)
            #pragma unroll
            for (int f = 0; f < 4; f++)
                #pragma unroll
                for (int k = 0; k < 4; k++) sacc[mf][f][k] = 0.f;
        const uint32_t kB0 = sm0 + SK_OFF + (uint32_t)buf * 32768u
                           + (uint32_t)(32 * wn + rB_) * 512u;
        const uint32_t kB1 = kB0 + 8192u;    // +16 key rows
        #pragma unroll
        for (int ks = 0; ks < 16; ks++) {
            uint32_t aq0[4], aq1[4], b0[4], b1[4];
            uint32_t ao = (uint32_t)(((2 * ks + cAo) ^ xs) << 4);
            ldm4(aq0, qA0 + ao);
            ldm4(aq1, qA1 + ao);
            uint32_t ko = (uint32_t)(((2 * ks + cBo) ^ xs) << 4);
            ldm4(b0, kB0 + ko);
            ldm4(b1, kB1 + ko);
            mma16(sacc[0][0], aq0, b0[0], b0[1]);
            mma16(sacc[0][1], aq0, b0[2], b0[3]);
            mma16(sacc[0][2], aq0, b1[0], b1[1]);
            mma16(sacc[0][3], aq0, b1[2], b1[3]);
            mma16(sacc[1][0], aq1, b0[0], b0[1]);
            mma16(sacc[1][1], aq1, b0[2], b0[3]);
            mma16(sacc[1][2], aq1, b1[0], b1[1]);
            mma16(sacc[1][3], aq1, b1[2], b1[3]);
        }

        // ---- softmax (max-free) -> sP bf16, accumulate l ----
        #pragma unroll
        for (int mf = 0; mf < 2; mf++) {
            char* p0p = smc + SP_OFF + (32 * wm + 16 * mf + g) * 128 + 4 * t;
            char* p1p = p0p + 8 * 128;
            #pragma unroll
            for (int f = 0; f < 4; f++) {
                float e0 = ex2(sacc[mf][f][0] * EC);
                float e1 = ex2(sacc[mf][f][1] * EC);
                float e2 = ex2(sacc[mf][f][2] * EC);
                float e3 = ex2(sacc[mf][f][3] * EC);
                lsum[mf][0] += e0 + e1;
                lsum[mf][1] += e2 + e3;
                int off = ((4 * wn + f) ^ g) << 4;
                *(uint32_t*)(p0p + off) = bf2(e0, e1);
                *(uint32_t*)(p1p + off) = bf2(e2, e3);
            }
        }
        __syncthreads();

        // ---- H += P V (warp tile 32 x 128; wn = channel half) ----
        const uint32_t vB = sm0 + SV_OFF + (uint32_t)buf * 32768u
                          + (uint32_t)(128 * wn + rB_) * 128u;
        #pragma unroll
        for (int ks = 0; ks < 4; ks++) {
            uint32_t ap0[4], ap1[4];
            uint32_t po = (uint32_t)(((2 * ks + cAo) ^ xs) << 4);
            ldm4(ap0, pA0 + po);
            ldm4(ap1, pA1 + po);
            uint32_t vo = (uint32_t)(((2 * ks + cBo) ^ xs) << 4);
            #pragma unroll
            for (int nb = 0; nb < 8; nb++) {
                uint32_t bv[4];
                ldm4(bv, vB + (uint32_t)nb * 2048u + vo);
                mma16(hacc[0][2 * nb],     ap0, bv[0], bv[1]);
                mma16(hacc[0][2 * nb + 1], ap0, bv[2], bv[3]);
                mma16(hacc[1][2 * nb],     ap1, bv[0], bv[1]);
                mma16(hacc[1][2 * nb + 1], ap1, bv[2], bv[3]);
            }
        }
        __syncthreads();
    }

    // ---- l reduction (t lanes, then wn halves via smem) ----
    float* sl = (float*)(smc + SL_OFF);
    #pragma unroll
    for (int mf = 0; mf < 2; mf++) {
        #pragma unroll
        for (int h = 0; h < 2; h++) {
            lsum[mf][h] += __shfl_xor_sync(0xffffffffu, lsum[mf][h], 1);
            lsum[mf][h] += __shfl_xor_sync(0xffffffffu, lsum[mf][h], 2);
        }
        if (t == 0) {
            sl[wn * QR + 32 * wm + 16 * mf + g]     = lsum[mf][0];
            sl[wn * QR + 32 * wm + 16 * mf + 8 + g] = lsum[mf][1];
        }
    }
    __syncthreads();

    // ---- epilogue: out[b][c][n] += h / l ----
    float* ob = out + (size_t)b * CDIM * NDIM + n0;
    #pragma unroll
    for (int mf = 0; mf < 2; mf++) {
        const int r0 = 32 * wm + 16 * mf + g;
        float li0 = 1.f / (sl[r0]     + sl[QR + r0]);
        float li1 = 1.f / (sl[r0 + 8] + sl[QR + r0 + 8]);
        #pragma unroll
        for (int nf = 0; nf < 16; nf++) {
            int c = 128 * wn + 8 * nf + 2 * t;
            float* d0 = ob + (size_t)c * NDIM + r0;
            float* d1 = d0 + NDIM;
            d0[0] += hacc[mf][nf][0] * li0;
            d1[0] += hacc[mf][nf][1] * li0;
            d0[8] += hacc[mf][nf][2] * li1;
            d1[8] += hacc[mf][nf][3] * li1;
        }
    }
}

extern "C" void kernel_launch(void* const* d_in, const int* in_sizes, int n_in,
                              void* d_out, int out_size)
{
    const float* x  = (const float*)d_in[0];
    const float* Wq = (const float*)d_in[1];
    const float* bq = (const float*)d_in[2];
    const float* Wk = (const float*)d_in[3];
    const float* bk = (const float*)d_in[4];
    const float* Wv = (const float*)d_in[5];
    const float* bv = (const float*)d_in[6];
    const float* Wp = (const float*)d_in[7];
    const float* bp = (const float*)d_in[8];
    float* out = (float*)d_out;

    cudaFuncSetAttribute(proj_mma_kernel,
                         cudaFuncAttributeMaxDynamicSharedMemorySize, PSM_BYTES);
    cudaFuncSetAttribute(attn_kernel,
                         cudaFuncAttributeMaxDynamicSharedMemorySize, SM_BYTES);

    proj_mma_kernel<<<dim3(32, 4, 8), 256, PSM_BYTES>>>(
        x, Wq, bq, Wk, bk, Wv, bv, Wp, bp, out);
    attn_kernel<<<dim3(NDIM / QR, BDIM), 256, SM_BYTES>>>(out);
}

// round 10
// speedup vs baseline: 8.5218x; 1.0303x over previous
#include <cuda_runtime.h>
#include <cuda_bf16.h>
#include <math.h>
#include <stdint.h>

#define CDIM 256
#define NDIM 4096
#define BDIM 8
#define QR   128
#define TK   64
#define NT   (NDIM / TK)   // 64

__device__ __nv_bfloat16 g_q[(size_t)BDIM * NDIM * CDIM];   // [b][n][c]
__device__ __nv_bfloat16 g_k[(size_t)BDIM * NDIM * CDIM];   // [b][n][c]
__device__ __nv_bfloat16 g_v[(size_t)BDIM * NDIM * CDIM];   // [b][c][n] (transposed)

// ---- attn smem byte offsets (tile swizzle: 16B chunk ^= row&7) ----
#define SQ_OFF 0u          // 128 x 256 bf16 = 64KB
#define SK_OFF 65536u      // 2 x (64 x 256 bf16) = 64KB
#define SV_OFF 131072u     // 2 x (256 x 64 bf16) = 64KB
#define SM_BYTES 196608u

// ---- proj smem float offsets ----
#define PXH 0            // 32 x 136
#define PXL 4352
#define PWH 8704         // 256 x 36
#define PWL 17920
#define PSM_FLOATS 27136
#define PSM_BYTES (PSM_FLOATS * 4)

// ---------------- helpers ----------------
__device__ __forceinline__ uint32_t smem_u32(const void* p) {
    uint32_t a;
    asm("{ .reg .u64 t; cvta.to.shared.u64 t, %1; cvt.u32.u64 %0, t; }" : "=r"(a) : "l"(p));
    return a;
}
__device__ __forceinline__ float ex2(float x) {
    float y; asm("ex2.approx.f32 %0, %1;" : "=f"(y) : "f"(x)); return y;
}
__device__ __forceinline__ float to_tf32(float x) {
    float r; asm("cvt.rna.tf32.f32 %0, %1;" : "=f"(r) : "f"(x)); return r;
}
__device__ __forceinline__ uint32_t bf2(float lo, float hi) {
    __nv_bfloat162 h = __float22bfloat162_rn(make_float2(lo, hi));
    return *(uint32_t*)&h;
}
__device__ __forceinline__ void cp16(uint32_t saddr, const void* gaddr) {
    asm volatile("cp.async.cg.shared.global [%0], [%1], 16;" :: "r"(saddr), "l"(gaddr));
}
__device__ __forceinline__ void cp_commit() {
    asm volatile("cp.async.commit_group;" ::: "memory");
}
template <int N>
__device__ __forceinline__ void cp_wait() {
    asm volatile("cp.async.wait_group %0;" :: "n"(N) : "memory");
}
__device__ __forceinline__ void ldm4(uint32_t* r, uint32_t addr) {
    asm volatile("ldmatrix.sync.aligned.m8n8.x4.shared.b16 {%0,%1,%2,%3}, [%4];"
        : "=r"(r[0]), "=r"(r[1]), "=r"(r[2]), "=r"(r[3]) : "r"(addr));
}
__device__ __forceinline__ void mma16(float* d, const uint32_t* a, uint32_t b0, uint32_t b1) {
    asm volatile("mma.sync.aligned.m16n8k16.row.col.f32.bf16.bf16.f32 "
        "{%0,%1,%2,%3}, {%4,%5,%6,%7}, {%8,%9}, {%0,%1,%2,%3};"
        : "+f"(d[0]), "+f"(d[1]), "+f"(d[2]), "+f"(d[3])
        : "r"(a[0]), "r"(a[1]), "r"(a[2]), "r"(a[3]), "r"(b0), "r"(b1));
}
__device__ __forceinline__ void mma8(float* d, float a0, float a1, float a2, float a3,
                                     float b0, float b1) {
    asm volatile("mma.sync.aligned.m16n8k8.row.col.f32.tf32.tf32.f32 "
        "{%0,%1,%2,%3}, {%4,%5,%6,%7}, {%8,%9}, {%0,%1,%2,%3};"
        : "+f"(d[0]), "+f"(d[1]), "+f"(d[2]), "+f"(d[3])
        : "r"(__float_as_uint(a0)), "r"(__float_as_uint(a1)),
          "r"(__float_as_uint(a2)), "r"(__float_as_uint(a3)),
          "r"(__float_as_uint(b0)), "r"(__float_as_uint(b1)));
}

// ---------------- tensor-core projection (unchanged from R7/R9) ------------
__global__ __launch_bounds__(256, 1) void proj_mma_kernel(
    const float* __restrict__ x,
    const float* __restrict__ Wq, const float* __restrict__ bq,
    const float* __restrict__ Wk, const float* __restrict__ bk,
    const float* __restrict__ Wv, const float* __restrict__ bv,
    const float* __restrict__ Wp, const float* __restrict__ bp,
    float* __restrict__ out)
{
    extern __shared__ float ps[];
    float* sXh = ps + PXH;
    float* sXl = ps + PXL;
    float* sWh = ps + PWH;
    float* sWl = ps + PWL;

    const int p  = blockIdx.y;
    const int b  = blockIdx.z;
    const int n0 = blockIdx.x * 128;
    const float* W; const float* bias;
    if (p == 0)      { W = Wq; bias = bq; }
    else if (p == 1) { W = Wk; bias = bk; }
    else if (p == 2) { W = Wv; bias = bv; }
    else             { W = Wp; bias = bp; }
    const bool do_lo = (p == 3);

    const int tid = threadIdx.x, lane = tid & 31, w = tid >> 5;
    const int g = lane >> 2, t = lane & 3;
    const int wx = w >> 1;
    const int wy = w & 1;
    const float* xb = x + (size_t)b * CDIM * NDIM + n0;

    float4 xr[4], wr[8];
    #pragma unroll
    for (int j = 0; j < 4; j++) {
        int idx = tid + 256 * j, r = idx >> 5, ch = idx & 31;
        xr[j] = *(const float4*)(xb + (size_t)r * NDIM + ch * 4);
    }
    #pragma unroll
    for (int j = 0; j < 8; j++) {
        int idx = tid + 256 * j, r = idx >> 3, ch = idx & 7;
        wr[j] = *(const float4*)(W + r * CDIM + ch * 4);
    }

    float acc[4][8][4];
    #pragma unroll
    for (int mf = 0; mf < 4; mf++)
        #pragma unroll
        for (int nf = 0; nf < 8; nf++)
            #pragma unroll
            for (int k = 0; k < 4; k++) acc[mf][nf][k] = 0.f;

    for (int kc = 0; kc < 8; kc++) {
        #pragma unroll
        for (int j = 0; j < 4; j++) {
            int idx = tid + 256 * j, r = idx >> 5, ch = idx & 31;
            float4 v = xr[j];
            float4 h = make_float4(to_tf32(v.x), to_tf32(v.y), to_tf32(v.z), to_tf32(v.w));
            *(float4*)(sXh + r * 136 + ch * 4) = h;
            if (do_lo)
                *(float4*)(sXl + r * 136 + ch * 4) =
                    make_float4(to_tf32(v.x - h.x), to_tf32(v.y - h.y),
                                to_tf32(v.z - h.z), to_tf32(v.w - h.w));
        }
        #pragma unroll
        for (int j = 0; j < 8; j++) {
            int idx = tid + 256 * j, r = idx >> 3, ch = idx & 7;
            float4 v = wr[j];
            float4 h = make_float4(to_tf32(v.x), to_tf32(v.y), to_tf32(v.z), to_tf32(v.w));
            *(float4*)(sWh + r * 36 + ch * 4) = h;
            if (do_lo)
                *(float4*)(sWl + r * 36 + ch * 4) =
                    make_float4(to_tf32(v.x - h.x), to_tf32(v.y - h.y),
                                to_tf32(v.z - h.z), to_tf32(v.w - h.w));
        }
        __syncthreads();

        if (kc < 7) {
            const float* xn = xb + (size_t)(kc + 1) * 32 * NDIM;
            #pragma unroll
            for (int j = 0; j < 4; j++) {
                int idx = tid + 256 * j, r = idx >> 5, ch = idx & 31;
                xr[j] = *(const float4*)(xn + (size_t)r * NDIM + ch * 4);
            }
            const float* wn = W + (kc + 1) * 32;
            #pragma unroll
            for (int j = 0; j < 8; j++) {
                int idx = tid + 256 * j, r = idx >> 3, ch = idx & 7;
                wr[j] = *(const float4*)(wn + r * CDIM + ch * 4);
            }
        }

        #pragma unroll
        for (int ks = 0; ks < 4; ks++) {
            const int c0i = 8 * ks + t;
            float ah[4][4], bh[8][2];
            if (p < 2) {
                const float* x0 = sXh + c0i * 136 + 64 * wy;
                const float* x4 = x0 + 4 * 136;
                #pragma unroll
                for (int mf = 0; mf < 4; mf++) {
                    ah[mf][0] = x0[16 * mf + g];
                    ah[mf][1] = x0[16 * mf + 8 + g];
                    ah[mf][2] = x4[16 * mf + g];
                    ah[mf][3] = x4[16 * mf + 8 + g];
                }
                #pragma unroll
                for (int nf = 0; nf < 8; nf++) {
                    const float* wrow = sWh + (64 * wx + 8 * nf + g) * 36;
                    bh[nf][0] = wrow[c0i];
                    bh[nf][1] = wrow[c0i + 4];
                }
                #pragma unroll
                for (int mf = 0; mf < 4; mf++)
                    #pragma unroll
                    for (int nf = 0; nf < 8; nf++)
                        mma8(acc[mf][nf], ah[mf][0], ah[mf][1], ah[mf][2], ah[mf][3],
                             bh[nf][0], bh[nf][1]);
            } else {
                #pragma unroll
                for (int mf = 0; mf < 4; mf++) {
                    const float* w0 = sWh + (64 * wx + 16 * mf + g) * 36;
                    const float* w8 = w0 + 8 * 36;
                    ah[mf][0] = w0[c0i];
                    ah[mf][1] = w8[c0i];
                    ah[mf][2] = w0[c0i + 4];
                    ah[mf][3] = w8[c0i + 4];
                }
                const float* x0 = sXh + c0i * 136 + 64 * wy;
                const float* x4 = x0 + 4 * 136;
                #pragma unroll
                for (int nf = 0; nf < 8; nf++) {
                    bh[nf][0] = x0[8 * nf + g];
                    bh[nf][1] = x4[8 * nf + g];
                }
                #pragma unroll
                for (int mf = 0; mf < 4; mf++)
                    #pragma unroll
                    for (int nf = 0; nf < 8; nf++)
                        mma8(acc[mf][nf], ah[mf][0], ah[mf][1], ah[mf][2], ah[mf][3],
                             bh[nf][0], bh[nf][1]);
                if (do_lo) {
                    float al[4][4], bl[8][2];
                    #pragma unroll
                    for (int mf = 0; mf < 4; mf++) {
                        const float* w0 = sWl + (64 * wx + 16 * mf + g) * 36;
                        const float* w8 = w0 + 8 * 36;
                        al[mf][0] = w0[c0i];
                        al[mf][1] = w8[c0i];
                        al[mf][2] = w0[c0i + 4];
                        al[mf][3] = w8[c0i + 4];
                    }
                    const float* l0 = sXl + c0i * 136 + 64 * wy;
                    const float* l4 = l0 + 4 * 136;
                    #pragma unroll
                    for (int nf = 0; nf < 8; nf++) {
                        bl[nf][0] = l0[8 * nf + g];
                        bl[nf][1] = l4[8 * nf + g];
                    }
                    #pragma unroll
                    for (int mf = 0; mf < 4; mf++)
                        #pragma unroll
                        for (int nf = 0; nf < 8; nf++) {
                            mma8(acc[mf][nf], ah[mf][0], ah[mf][1], ah[mf][2], ah[mf][3],
                                 bl[nf][0], bl[nf][1]);
                            mma8(acc[mf][nf], al[mf][0], al[mf][1], al[mf][2], al[mf][3],
                                 bh[nf][0], bh[nf][1]);
                        }
                }
            }
        }
        __syncthreads();
    }

    if (p < 2) {
        __nv_bfloat16* dst = ((p == 0) ? g_q : g_k) + (size_t)b * NDIM * CDIM;
        #pragma unroll
        for (int mf = 0; mf < 4; mf++) {
            int n = n0 + 64 * wy + 16 * mf + g;
            #pragma unroll
            for (int nf = 0; nf < 8; nf++) {
                int o = 64 * wx + 8 * nf + 2 * t;
                float2 bs = *(const float2*)(bias + o);
                *(uint32_t*)(dst + (size_t)n * CDIM + o) =
                    bf2(acc[mf][nf][0] + bs.x, acc[mf][nf][1] + bs.y);
                *(uint32_t*)(dst + (size_t)(n + 8) * CDIM + o) =
                    bf2(acc[mf][nf][2] + bs.x, acc[mf][nf][3] + bs.y);
            }
        }
    } else if (p == 2) {
        __nv_bfloat16* dst = g_v + (size_t)b * CDIM * NDIM;
        #pragma unroll
        for (int mf = 0; mf < 4; mf++) {
            int o = 64 * wx + 16 * mf + g;
            float b0 = bias[o], b8 = bias[o + 8];
            #pragma unroll
            for (int nf = 0; nf < 8; nf++) {
                int n = n0 + 64 * wy + 8 * nf + 2 * t;
                *(uint32_t*)(dst + (size_t)o * NDIM + n) =
                    bf2(acc[mf][nf][0] + b0, acc[mf][nf][1] + b0);
                *(uint32_t*)(dst + (size_t)(o + 8) * NDIM + n) =
                    bf2(acc[mf][nf][2] + b8, acc[mf][nf][3] + b8);
            }
        }
    } else {
        float* dst = out + (size_t)b * CDIM * NDIM;
        #pragma unroll
        for (int mf = 0; mf < 4; mf++) {
            int o = 64 * wx + 16 * mf + g;
            float b0 = bias[o], b8 = bias[o + 8];
            #pragma unroll
            for (int nf = 0; nf < 8; nf++) {
                int n = n0 + 64 * wy + 8 * nf + 2 * t;
                *(float2*)(dst + (size_t)o * NDIM + n) =
                    make_float2(acc[mf][nf][0] + b0, acc[mf][nf][1] + b0);
                *(float2*)(dst + (size_t)(o + 8) * NDIM + n) =
                    make_float2(acc[mf][nf][2] + b8, acc[mf][nf][3] + b8);
            }
        }
    }
}

// ---------------- K/V tile loader (cp.async, bf16, swizzled) ---------------
__device__ __forceinline__ void load_kv(uint32_t sm0, const __nv_bfloat16* kb,
                                        const __nv_bfloat16* vb, int i, int buf, int tid)
{
    const int m0 = i * TK;
    const uint32_t sk = sm0 + SK_OFF + (uint32_t)buf * 32768u;
    const uint32_t sv = sm0 + SV_OFF + (uint32_t)buf * 32768u;
    #pragma unroll
    for (int j = 0; j < 8; j++) {          // K: 64 keys x 256 c
        int idx = tid + 256 * j, r = idx >> 5, ch = idx & 31;
        cp16(sk + (uint32_t)r * 512u + (uint32_t)((ch ^ (r & 7)) << 4),
             kb + (size_t)(m0 + r) * CDIM + ch * 8);
    }
    #pragma unroll
    for (int j = 0; j < 8; j++) {          // V^T: 256 c x 64 keys
        int idx = tid + 256 * j, r = idx >> 3, ch = idx & 7;
        cp16(sv + (uint32_t)r * 128u + (uint32_t)((ch ^ (r & 7)) << 4),
             vb + (size_t)r * NDIM + m0 + ch * 8);
    }
}

// ---------------- bf16 mma flash attention, register-resident P ------------
// grid (32, 8), 256 thr, 8 warps. Warp w owns q-rows [16w, 16w+16).
// S warp tile 16x64 (all keys); P stays in registers as PV A-fragments;
// PV warp tile 16x256 (all channels). One __syncthreads per tile.
__global__ __launch_bounds__(256, 1) void attn_kernel(float* __restrict__ out)
{
    extern __shared__ char smc[];
    const uint32_t sm0 = smem_u32(smc);
    const int tid = threadIdx.x, lane = tid & 31;
    const int w = tid >> 5;
    const int g = lane >> 2, t = lane & 3;
    const int b = blockIdx.y, n0 = blockIdx.x * QR;

    const __nv_bfloat16* qb = g_q + ((size_t)b * NDIM + n0) * CDIM;
    const __nv_bfloat16* kb = g_k + (size_t)b * NDIM * CDIM;
    const __nv_bfloat16* vb = g_v + (size_t)b * CDIM * NDIM;

    // prologue: Q (128x256) + tile0 in one cp.async group
    #pragma unroll
    for (int j = 0; j < 16; j++) {
        int idx = tid + 256 * j, r = idx >> 5, ch = idx & 31;
        cp16(sm0 + SQ_OFF + (uint32_t)r * 512u + (uint32_t)((ch ^ (r & 7)) << 4),
             qb + (size_t)r * CDIM + ch * 8);
    }
    load_kv(sm0, kb, vb, 0, 0, tid);
    cp_commit();

    // ldmatrix lane geometry
    const int rA  = ((lane >> 3) & 1) * 8 + (lane & 7);   // A row-in-16
    const int cAo = lane >> 4;
    const int rB_ = ((lane >> 4) & 1) * 8 + (lane & 7);   // B row-in-16
    const int cBo = (lane >> 3) & 1;
    const int xs  = lane & 7;                             // swizzle XOR
    const uint32_t qA = sm0 + SQ_OFF + (uint32_t)(16 * w + rA) * 512u;

    float hacc[32][4];
    #pragma unroll
    for (int nf = 0; nf < 32; nf++)
        #pragma unroll
        for (int k = 0; k < 4; k++) hacc[nf][k] = 0.f;
    float lsum0 = 0.f, lsum1 = 0.f;
    const float EC = 0.0901684400555602f;    // log2(e)/16

    for (int i = 0; i < NT; i++) {
        const int buf = i & 1;
        cp_wait<0>();                         // tile i resident
        __syncthreads();                      // everyone done with buf^1 reads
        if (i + 1 < NT) { load_kv(sm0, kb, vb, i + 1, buf ^ 1, tid); cp_commit(); }

        // ---- S = Q K^T (warp tile 16 rows x 64 keys) ----
        float sacc[8][4];
        #pragma unroll
        for (int f = 0; f < 8; f++)
            #pragma unroll
            for (int k = 0; k < 4; k++) sacc[f][k] = 0.f;
        const uint32_t kB = sm0 + SK_OFF + (uint32_t)buf * 32768u
                          + (uint32_t)rB_ * 512u;
        #pragma unroll
        for (int ks = 0; ks < 16; ks++) {
            uint32_t aq[4];
            ldm4(aq, qA + (uint32_t)(((2 * ks + cAo) ^ xs) << 4));
            uint32_t ko = (uint32_t)(((2 * ks + cBo) ^ xs) << 4);
            #pragma unroll
            for (int nf2 = 0; nf2 < 4; nf2++) {
                uint32_t bk[4];
                ldm4(bk, kB + (uint32_t)nf2 * 8192u + ko);
                mma16(sacc[2 * nf2],     aq, bk[0], bk[1]);
                mma16(sacc[2 * nf2 + 1], aq, bk[2], bk[3]);
            }
        }

        // ---- softmax (max-free) -> PV A-fragments in registers ----
        uint32_t pf[4][4];
        #pragma unroll
        for (int nf = 0; nf < 8; nf++) {
            float e0 = ex2(sacc[nf][0] * EC);
            float e1 = ex2(sacc[nf][1] * EC);
            float e2 = ex2(sacc[nf][2] * EC);
            float e3 = ex2(sacc[nf][3] * EC);
            lsum0 += e0 + e1;
            lsum1 += e2 + e3;
            pf[nf >> 1][(nf & 1) * 2 + 0] = bf2(e0, e1);
            pf[nf >> 1][(nf & 1) * 2 + 1] = bf2(e2, e3);
        }

        // ---- H += P V (warp tile 16 rows x 256 channels, k = 64 keys) ----
        const uint32_t vB = sm0 + SV_OFF + (uint32_t)buf * 32768u
                          + (uint32_t)rB_ * 128u;
        #pragma unroll
        for (int ks = 0; ks < 4; ks++) {
            uint32_t vo = (uint32_t)(((2 * ks + cBo) ^ xs) << 4);
            #pragma unroll
            for (int nb = 0; nb < 16; nb++) {
                uint32_t bv[4];
                ldm4(bv, vB + (uint32_t)nb * 2048u + vo);
                mma16(hacc[2 * nb],     pf[ks], bv[0], bv[1]);
                mma16(hacc[2 * nb + 1], pf[ks], bv[2], bv[3]);
            }
        }
    }

    // ---- l reduction (t lanes only; warp owns its rows) ----
    lsum0 += __shfl_xor_sync(0xffffffffu, lsum0, 1);
    lsum0 += __shfl_xor_sync(0xffffffffu, lsum0, 2);
    lsum1 += __shfl_xor_sync(0xffffffffu, lsum1, 1);
    lsum1 += __shfl_xor_sync(0xffffffffu, lsum1, 2);
    const float li0 = 1.f / lsum0;
    const float li1 = 1.f / lsum1;

    // ---- epilogue: out[b][c][n] += h / l ----
    const int r0 = 16 * w + g;
    float* ob = out + (size_t)b * CDIM * NDIM + n0;
    #pragma unroll
    for (int nf = 0; nf < 32; nf++) {
        int c = 8 * nf + 2 * t;
        float* d0 = ob + (size_t)c * NDIM + r0;
        float* d1 = d0 + NDIM;
        d0[0] += hacc[nf][0] * li0;
        d1[0] += hacc[nf][1] * li0;
        d0[8] += hacc[nf][2] * li1;
        d1[8] += hacc[nf][3] * li1;
    }
}

extern "C" void kernel_launch(void* const* d_in, const int* in_sizes, int n_in,
                              void* d_out, int out_size)
{
    const float* x  = (const float*)d_in[0];
    const float* Wq = (const float*)d_in[1];
    const float* bq = (const float*)d_in[2];
    const float* Wk = (const float*)d_in[3];
    const float* bk = (const float*)d_in[4];
    const float* Wv = (const float*)d_in[5];
    const float* bv = (const float*)d_in[6];
    const float* Wp = (const float*)d_in[7];
    const float* bp = (const float*)d_in[8];
    float* out = (float*)d_out;

    cudaFuncSetAttribute(proj_mma_kernel,
                         cudaFuncAttributeMaxDynamicSharedMemorySize, PSM_BYTES);
    cudaFuncSetAttribute(attn_kernel,
                         cudaFuncAttributeMaxDynamicSharedMemorySize, SM_BYTES);

    proj_mma_kernel<<<dim3(32, 4, 8), 256, PSM_BYTES>>>(
        x, Wq, bq, Wk, bk, Wv, bv, Wp, bp, out);
    attn_kernel<<<dim3(NDIM / QR, BDIM), 256, SM_BYTES>>>(out);
}

// round 11
// speedup vs baseline: 9.7434x; 1.1434x over previous
#include <cuda_runtime.h>
#include <cuda_bf16.h>
#include <math.h>
#include <stdint.h>

#define CDIM 256
#define NDIM 4096
#define BDIM 8
#define QR   128
#define TK   64
#define NT   (NDIM / TK)   // 64

__device__ __nv_bfloat16 g_q[(size_t)BDIM * NDIM * CDIM];   // [b][n][c]
__device__ __nv_bfloat16 g_k[(size_t)BDIM * NDIM * CDIM];   // [b][n][c]
__device__ __nv_bfloat16 g_v[(size_t)BDIM * NDIM * CDIM];   // [b][c][n] (transposed)
__device__ __nv_bfloat16 g_xh[(size_t)BDIM * NDIM * CDIM];  // x^T hi [b][n][c]
__device__ __nv_bfloat16 g_xl[(size_t)BDIM * NDIM * CDIM];  // x^T lo
__device__ __nv_bfloat16 g_wh[4 * CDIM * CDIM];             // W hi [p][o][c]
__device__ __nv_bfloat16 g_wl[4 * CDIM * CDIM];             // W lo

// ---- attn smem byte offsets (tile swizzle: 16B chunk ^= row&7) ----
#define SQ_OFF 0u          // 128 x 256 bf16 = 64KB
#define SK_OFF 65536u      // 2 x (64 x 256 bf16) = 64KB
#define SV_OFF 131072u     // 2 x (256 x 64 bf16) = 64KB
#define SM_BYTES 196608u

// ---- proj2 smem byte offsets (per buffer; 2 buffers) ----
#define P2_XH 0u           // 128n x 64c bf16 (row 128B, 8 chunks)
#define P2_XL 16384u
#define P2_WH 32768u       // 256o x 64c bf16
#define P2_WL 65536u
#define P2_BUF 98304u
#define P2_BYTES 196608u

// ---------------- helpers ----------------
__device__ __forceinline__ uint32_t smem_u32(const void* p) {
    uint32_t a;
    asm("{ .reg .u64 t; cvta.to.shared.u64 t, %1; cvt.u32.u64 %0, t; }" : "=r"(a) : "l"(p));
    return a;
}
__device__ __forceinline__ float ex2(float x) {
    float y; asm("ex2.approx.f32 %0, %1;" : "=f"(y) : "f"(x)); return y;
}
__device__ __forceinline__ uint32_t bf2(float lo, float hi) {
    __nv_bfloat162 h = __float22bfloat162_rn(make_float2(lo, hi));
    return *(uint32_t*)&h;
}
__device__ __forceinline__ void cp16(uint32_t saddr, const void* gaddr) {
    asm volatile("cp.async.cg.shared.global [%0], [%1], 16;" :: "r"(saddr), "l"(gaddr));
}
__device__ __forceinline__ void cp_commit() {
    asm volatile("cp.async.commit_group;" ::: "memory");
}
template <int N>
__device__ __forceinline__ void cp_wait() {
    asm volatile("cp.async.wait_group %0;" :: "n"(N) : "memory");
}
__device__ __forceinline__ void ldm4(uint32_t* r, uint32_t addr) {
    asm volatile("ldmatrix.sync.aligned.m8n8.x4.shared.b16 {%0,%1,%2,%3}, [%4];"
        : "=r"(r[0]), "=r"(r[1]), "=r"(r[2]), "=r"(r[3]) : "r"(addr));
}
__device__ __forceinline__ void mma16(float* d, const uint32_t* a, uint32_t b0, uint32_t b1) {
    asm volatile("mma.sync.aligned.m16n8k16.row.col.f32.bf16.bf16.f32 "
        "{%0,%1,%2,%3}, {%4,%5,%6,%7}, {%8,%9}, {%0,%1,%2,%3};"
        : "+f"(d[0]), "+f"(d[1]), "+f"(d[2]), "+f"(d[3])
        : "r"(a[0]), "r"(a[1]), "r"(a[2]), "r"(a[3]), "r"(b0), "r"(b1));
}

// ---------------- x transpose + hi/lo bf16 split ----------------------------
// grid (64 nblk, 4 cblk, 8 b), 256 thr. x [b][c][n] f32 -> g_xh/g_xl [b][n][c]
__global__ __launch_bounds__(256) void xpose_kernel(const float* __restrict__ x)
{
    __shared__ float sm[64 * 65];
    const int n0 = blockIdx.x * 64;
    const int c0 = blockIdx.y * 64;
    const int b  = blockIdx.z;
    const int tid = threadIdx.x;

    const float* xb = x + ((size_t)b * CDIM + c0) * NDIM + n0;
    #pragma unroll
    for (int j = 0; j < 4; j++) {        // 64c x 16 float4
        int idx = tid + 256 * j;
        int cc = idx >> 4, nn4 = idx & 15;
        float4 v = *(const float4*)(xb + (size_t)cc * NDIM + nn4 * 4);
        float* s = sm + cc * 65 + nn4 * 4;
        s[0] = v.x; s[1] = v.y; s[2] = v.z; s[3] = v.w;
    }
    __syncthreads();
    __nv_bfloat16* dh = g_xh + ((size_t)b * NDIM + n0) * CDIM + c0;
    __nv_bfloat16* dl = g_xl + ((size_t)b * NDIM + n0) * CDIM + c0;
    #pragma unroll
    for (int j = 0; j < 8; j++) {        // 64n x 32 c-pairs
        int idx = tid + 256 * j;
        int nn = idx >> 5, cp = idx & 31;
        float f0 = sm[(2 * cp)     * 65 + nn];
        float f1 = sm[(2 * cp + 1) * 65 + nn];
        float h0 = __bfloat162float(__float2bfloat16(f0));
        float h1 = __bfloat162float(__float2bfloat16(f1));
        *(uint32_t*)(dh + (size_t)nn * CDIM + 2 * cp) = bf2(f0, f1);
        *(uint32_t*)(dl + (size_t)nn * CDIM + 2 * cp) = bf2(f0 - h0, f1 - h1);
    }
}

// ---------------- W hi/lo convert: grid (4 p, 64), 256 thr ------------------
__global__ __launch_bounds__(256) void wconv_kernel(
    const float* __restrict__ Wq, const float* __restrict__ Wk,
    const float* __restrict__ Wv, const float* __restrict__ Wp)
{
    const int p = blockIdx.x;
    const float* W = (p == 0) ? Wq : (p == 1) ? Wk : (p == 2) ? Wv : Wp;
    int idx4 = blockIdx.y * 256 + threadIdx.x;   // 0..16383, 4 floats each
    float4 v = *(const float4*)(W + idx4 * 4);
    float hx = __bfloat162float(__float2bfloat16(v.x));
    float hy = __bfloat162float(__float2bfloat16(v.y));
    float hz = __bfloat162float(__float2bfloat16(v.z));
    float hw = __bfloat162float(__float2bfloat16(v.w));
    uint2 uh = make_uint2(bf2(v.x, v.y), bf2(v.z, v.w));
    uint2 ul = make_uint2(bf2(v.x - hx, v.y - hy), bf2(v.z - hz, v.w - hw));
    *(uint2*)(g_wh + (size_t)p * CDIM * CDIM + idx4 * 4) = uh;
    *(uint2*)(g_wl + (size_t)p * CDIM * CDIM + idx4 * 4) = ul;
}

// ---------------- proj2: bf16 mma projections -------------------------------
// grid (32 n-tiles, 4 p, 8 b), 256 thr. CTA: 128n x 256o, K chunks of 64.
// p<2 (q,k): D[n][o], A=Xt (M=n), B=W (N=o); chains Xh*Wh + Xl*Wh.
// p=2 (v):   D[o][n], A=W (M=o), B=Xt (N=n); chains Wh*Xh + Wh*Xl.
// p=3 (res): as v plus Wl*Xh (3-term compensated), fp32 out.
__global__ __launch_bounds__(256, 1) void proj2_kernel(
    const float* __restrict__ bq, const float* __restrict__ bk,
    const float* __restrict__ bv, const float* __restrict__ bp,
    float* __restrict__ out)
{
    extern __shared__ char smc[];
    const uint32_t sm0 = smem_u32(smc);
    const int n0 = blockIdx.x * 128;
    const int p  = blockIdx.y;
    const int b  = blockIdx.z;
    const float* bias = (p == 0) ? bq : (p == 1) ? bk : (p == 2) ? bv : bp;
    const bool qk = (p < 2);
    const bool res = (p == 3);

    const int tid = threadIdx.x, lane = tid & 31, w = tid >> 5;
    const int g = lane >> 2, t = lane & 3;
    // warp grid: qk -> wm=w&1 (M=n half), wn4=w>>1 (N=o quarter)
    //            v/res -> wm=w>>1 (M=o quarter), wn4=w&1 (N=n half)
    const int wm  = qk ? (w & 1) : (w >> 1);
    const int wn4 = qk ? (w >> 1) : (w & 1);

    const __nv_bfloat16* xh = g_xh + ((size_t)b * NDIM + n0) * CDIM;
    const __nv_bfloat16* xl = g_xl + ((size_t)b * NDIM + n0) * CDIM;
    const __nv_bfloat16* wh = g_wh + (size_t)p * CDIM * CDIM;
    const __nv_bfloat16* wl = g_wl + (size_t)p * CDIM * CDIM;

    // loader: chunk kc into buffer buf
    auto load_chunk = [&](int kc, int buf) {
        const uint32_t base = sm0 + (uint32_t)buf * P2_BUF;
        #pragma unroll
        for (int j = 0; j < 4; j++) {      // XH: 128 x 8
            int idx = tid + 256 * j, r = idx >> 3, ch = idx & 7;
            uint32_t so = (uint32_t)r * 128u + (uint32_t)((ch ^ (r & 7)) << 4);
            cp16(base + P2_XH + so, xh + (size_t)r * CDIM + kc * 64 + ch * 8);
        }
        #pragma unroll
        for (int j = 0; j < 4; j++) {      // XL
            int idx = tid + 256 * j, r = idx >> 3, ch = idx & 7;
            uint32_t so = (uint32_t)r * 128u + (uint32_t)((ch ^ (r & 7)) << 4);
            cp16(base + P2_XL + so, xl + (size_t)r * CDIM + kc * 64 + ch * 8);
        }
        #pragma unroll
        for (int j = 0; j < 8; j++) {      // WH: 256 x 8
            int idx = tid + 256 * j, r = idx >> 3, ch = idx & 7;
            uint32_t so = (uint32_t)r * 128u + (uint32_t)((ch ^ (r & 7)) << 4);
            cp16(base + P2_WH + so, wh + (size_t)r * CDIM + kc * 64 + ch * 8);
        }
        if (res) {
            #pragma unroll
            for (int j = 0; j < 8; j++) {  // WL
                int idx = tid + 256 * j, r = idx >> 3, ch = idx & 7;
                uint32_t so = (uint32_t)r * 128u + (uint32_t)((ch ^ (r & 7)) << 4);
                cp16(base + P2_WL + so, wl + (size_t)r * CDIM + kc * 64 + ch * 8);
            }
        }
    };

    load_chunk(0, 0);
    cp_commit();

    // ldmatrix lane geometry (identical to attn)
    const int rA  = ((lane >> 3) & 1) * 8 + (lane & 7);
    const int cAo = lane >> 4;
    const int rB_ = ((lane >> 4) & 1) * 8 + (lane & 7);
    const int cBo = (lane >> 3) & 1;
    const int xs  = lane & 7;

    float acc[4][8][4];
    #pragma unroll
    for (int mf = 0; mf < 4; mf++)
        #pragma unroll
        for (int nf = 0; nf < 8; nf++)
            #pragma unroll
            for (int k = 0; k < 4; k++) acc[mf][nf][k] = 0.f;

    for (int kc = 0; kc < 4; kc++) {
        const int buf = kc & 1;
        cp_wait<0>();
        __syncthreads();
        if (kc + 1 < 4) { load_chunk(kc + 1, buf ^ 1); cp_commit(); }

        const uint32_t base = sm0 + (uint32_t)buf * P2_BUF;
        // operand bases: A rows 64*wm.., B rows 64*wn4..
        const uint32_t offA1 = qk ? P2_XH : P2_WH;   // primary A
        const uint32_t offA2 = qk ? P2_XL : P2_WL;   // secondary A (qk: Xl; res: Wl)
        const uint32_t offB1 = qk ? P2_WH : P2_XH;   // primary B
        const uint32_t offB2 = P2_XL;                 // v/res secondary B
        const uint32_t aBase = base + (uint32_t)(64 * wm) * 128u + (uint32_t)rA * 128u;
        const uint32_t bBase = base + (uint32_t)(64 * wn4) * 128u + (uint32_t)rB_ * 128u;

        #pragma unroll
        for (int ks = 0; ks < 4; ks++) {
            const uint32_t ao = (uint32_t)(((2 * ks + cAo) ^ xs) << 4);
            const uint32_t bo = (uint32_t)(((2 * ks + cBo) ^ xs) << 4);
            // B primary frags (4 nf2 x 4)
            uint32_t b1[4][4];
            #pragma unroll
            for (int nf2 = 0; nf2 < 4; nf2++)
                ldm4(b1[nf2], bBase + offB1 + (uint32_t)nf2 * 2048u + bo);
            if (qk) {
                #pragma unroll
                for (int mf = 0; mf < 4; mf++) {
                    uint32_t ah[4], al[4];
                    ldm4(ah, aBase + offA1 + (uint32_t)mf * 2048u + ao);
                    ldm4(al, aBase + offA2 + (uint32_t)mf * 2048u + ao);
                    #pragma unroll
                    for (int nf2 = 0; nf2 < 4; nf2++) {
                        mma16(acc[mf][2 * nf2],     ah, b1[nf2][0], b1[nf2][1]);
                        mma16(acc[mf][2 * nf2 + 1], ah, b1[nf2][2], b1[nf2][3]);
                        mma16(acc[mf][2 * nf2],     al, b1[nf2][0], b1[nf2][1]);
                        mma16(acc[mf][2 * nf2 + 1], al, b1[nf2][2], b1[nf2][3]);
                    }
                }
            } else {
                uint32_t b2[4][4];
                #pragma unroll
                for (int nf2 = 0; nf2 < 4; nf2++)
                    ldm4(b2[nf2], bBase + offB2 + (uint32_t)nf2 * 2048u + bo);
                #pragma unroll
                for (int mf = 0; mf < 4; mf++) {
                    uint32_t ah[4];
                    ldm4(ah, aBase + offA1 + (uint32_t)mf * 2048u + ao);
                    #pragma unroll
                    for (int nf2 = 0; nf2 < 4; nf2++) {
                        mma16(acc[mf][2 * nf2],     ah, b1[nf2][0], b1[nf2][1]);
                        mma16(acc[mf][2 * nf2 + 1], ah, b1[nf2][2], b1[nf2][3]);
                        mma16(acc[mf][2 * nf2],     ah, b2[nf2][0], b2[nf2][1]);
                        mma16(acc[mf][2 * nf2 + 1], ah, b2[nf2][2], b2[nf2][3]);
                    }
                    if (res) {
                        uint32_t al[4];
                        ldm4(al, aBase + offA2 + (uint32_t)mf * 2048u + ao);
                        #pragma unroll
                        for (int nf2 = 0; nf2 < 4; nf2++) {
                            mma16(acc[mf][2 * nf2],     al, b1[nf2][0], b1[nf2][1]);
                            mma16(acc[mf][2 * nf2 + 1], al, b1[nf2][2], b1[nf2][3]);
                        }
                    }
                }
            }
        }
        __syncthreads();
    }

    // ---- epilogue ----
    if (qk) {
        __nv_bfloat16* dst = ((p == 0) ? g_q : g_k) + (size_t)b * NDIM * CDIM;
        #pragma unroll
        for (int mf = 0; mf < 4; mf++) {
            int n = n0 + 64 * wm + 16 * mf + g;
            #pragma unroll
            for (int nf = 0; nf < 8; nf++) {
                int o = 64 * wn4 + 8 * nf + 2 * t;
                float2 bs = *(const float2*)(bias + o);
                *(uint32_t*)(dst + (size_t)n * CDIM + o) =
                    bf2(acc[mf][nf][0] + bs.x, acc[mf][nf][1] + bs.y);
                *(uint32_t*)(dst + (size_t)(n + 8) * CDIM + o) =
                    bf2(acc[mf][nf][2] + bs.x, acc[mf][nf][3] + bs.y);
            }
        }
    } else if (p == 2) {
        __nv_bfloat16* dst = g_v + (size_t)b * CDIM * NDIM;
        #pragma unroll
        for (int mf = 0; mf < 4; mf++) {
            int o = 64 * wm + 16 * mf + g;
            float b0 = bias[o], b8 = bias[o + 8];
            #pragma unroll
            for (int nf = 0; nf < 8; nf++) {
                int n = n0 + 64 * wn4 + 8 * nf + 2 * t;
                *(uint32_t*)(dst + (size_t)o * NDIM + n) =
                    bf2(acc[mf][nf][0] + b0, acc[mf][nf][1] + b0);
                *(uint32_t*)(dst + (size_t)(o + 8) * NDIM + n) =
                    bf2(acc[mf][nf][2] + b8, acc[mf][nf][3] + b8);
            }
        }
    } else {
        float* dst = out + (size_t)b * CDIM * NDIM;
        #pragma unroll
        for (int mf = 0; mf < 4; mf++) {
            int o = 64 * wm + 16 * mf + g;
            float b0 = bias[o], b8 = bias[o + 8];
            #pragma unroll
            for (int nf = 0; nf < 8; nf++) {
                int n = n0 + 64 * wn4 + 8 * nf + 2 * t;
                *(float2*)(dst + (size_t)o * NDIM + n) =
                    make_float2(acc[mf][nf][0] + b0, acc[mf][nf][1] + b0);
                *(float2*)(dst + (size_t)(o + 8) * NDIM + n) =
                    make_float2(acc[mf][nf][2] + b8, acc[mf][nf][3] + b8);
            }
        }
    }
}

// ---------------- K/V tile loader (cp.async, bf16, swizzled) ---------------
__device__ __forceinline__ void load_kv(uint32_t sm0, const __nv_bfloat16* kb,
                                        const __nv_bfloat16* vb, int i, int buf, int tid)
{
    const int m0 = i * TK;
    const uint32_t sk = sm0 + SK_OFF + (uint32_t)buf * 32768u;
    const uint32_t sv = sm0 + SV_OFF + (uint32_t)buf * 32768u;
    #pragma unroll
    for (int j = 0; j < 8; j++) {          // K: 64 keys x 256 c
        int idx = tid + 256 * j, r = idx >> 5, ch = idx & 31;
        cp16(sk + (uint32_t)r * 512u + (uint32_t)((ch ^ (r & 7)) << 4),
             kb + (size_t)(m0 + r) * CDIM + ch * 8);
    }
    #pragma unroll
    for (int j = 0; j < 8; j++) {          // V^T: 256 c x 64 keys
        int idx = tid + 256 * j, r = idx >> 3, ch = idx & 7;
        cp16(sv + (uint32_t)r * 128u + (uint32_t)((ch ^ (r & 7)) << 4),
             vb + (size_t)r * NDIM + m0 + ch * 8);
    }
}

// ---------------- bf16 mma flash attention (unchanged from R10) ------------
__global__ __launch_bounds__(256, 1) void attn_kernel(float* __restrict__ out)
{
    extern __shared__ char smc[];
    const uint32_t sm0 = smem_u32(smc);
    const int tid = threadIdx.x, lane = tid & 31;
    const int w = tid >> 5;
    const int g = lane >> 2, t = lane & 3;
    const int b = blockIdx.y, n0 = blockIdx.x * QR;

    const __nv_bfloat16* qb = g_q + ((size_t)b * NDIM + n0) * CDIM;
    const __nv_bfloat16* kb = g_k + (size_t)b * NDIM * CDIM;
    const __nv_bfloat16* vb = g_v + (size_t)b * CDIM * NDIM;

    #pragma unroll
    for (int j = 0; j < 16; j++) {
        int idx = tid + 256 * j, r = idx >> 5, ch = idx & 31;
        cp16(sm0 + SQ_OFF + (uint32_t)r * 512u + (uint32_t)((ch ^ (r & 7)) << 4),
             qb + (size_t)r * CDIM + ch * 8);
    }
    load_kv(sm0, kb, vb, 0, 0, tid);
    cp_commit();

    const int rA  = ((lane >> 3) & 1) * 8 + (lane & 7);
    const int cAo = lane >> 4;
    const int rB_ = ((lane >> 4) & 1) * 8 + (lane & 7);
    const int cBo = (lane >> 3) & 1;
    const int xs  = lane & 7;
    const uint32_t qA = sm0 + SQ_OFF + (uint32_t)(16 * w + rA) * 512u;

    float hacc[32][4];
    #pragma unroll
    for (int nf = 0; nf < 32; nf++)
        #pragma unroll
        for (int k = 0; k < 4; k++) hacc[nf][k] = 0.f;
    float lsum0 = 0.f, lsum1 = 0.f;
    const float EC = 0.0901684400555602f;    // log2(e)/16

    for (int i = 0; i < NT; i++) {
        const int buf = i & 1;
        cp_wait<0>();
        __syncthreads();
        if (i + 1 < NT) { load_kv(sm0, kb, vb, i + 1, buf ^ 1, tid); cp_commit(); }

        float sacc[8][4];
        #pragma unroll
        for (int f = 0; f < 8; f++)
            #pragma unroll
            for (int k = 0; k < 4; k++) sacc[f][k] = 0.f;
        const uint32_t kB = sm0 + SK_OFF + (uint32_t)buf * 32768u
                          + (uint32_t)rB_ * 512u;
        #pragma unroll
        for (int ks = 0; ks < 16; ks++) {
            uint32_t aq[4];
            ldm4(aq, qA + (uint32_t)(((2 * ks + cAo) ^ xs) << 4));
            uint32_t ko = (uint32_t)(((2 * ks + cBo) ^ xs) << 4);
            #pragma unroll
            for (int nf2 = 0; nf2 < 4; nf2++) {
                uint32_t bk[4];
                ldm4(bk, kB + (uint32_t)nf2 * 8192u + ko);
                mma16(sacc[2 * nf2],     aq, bk[0], bk[1]);
                mma16(sacc[2 * nf2 + 1], aq, bk[2], bk[3]);
            }
        }

        uint32_t pf[4][4];
        #pragma unroll
        for (int nf = 0; nf < 8; nf++) {
            float e0 = ex2(sacc[nf][0] * EC);
            float e1 = ex2(sacc[nf][1] * EC);
            float e2 = ex2(sacc[nf][2] * EC);
            float e3 = ex2(sacc[nf][3] * EC);
            lsum0 += e0 + e1;
            lsum1 += e2 + e3;
            pf[nf >> 1][(nf & 1) * 2 + 0] = bf2(e0, e1);
            pf[nf >> 1][(nf & 1) * 2 + 1] = bf2(e2, e3);
        }

        const uint32_t vB = sm0 + SV_OFF + (uint32_t)buf * 32768u
                          + (uint32_t)rB_ * 128u;
        #pragma unroll
        for (int ks = 0; ks < 4; ks++) {
            uint32_t vo = (uint32_t)(((2 * ks + cBo) ^ xs) << 4);
            #pragma unroll
            for (int nb = 0; nb < 16; nb++) {
                uint32_t bv[4];
                ldm4(bv, vB + (uint32_t)nb * 2048u + vo);
                mma16(hacc[2 * nb],     pf[ks], bv[0], bv[1]);
                mma16(hacc[2 * nb + 1], pf[ks], bv[2], bv[3]);
            }
        }
    }

    lsum0 += __shfl_xor_sync(0xffffffffu, lsum0, 1);
    lsum0 += __shfl_xor_sync(0xffffffffu, lsum0, 2);
    lsum1 += __shfl_xor_sync(0xffffffffu, lsum1, 1);
    lsum1 += __shfl_xor_sync(0xffffffffu, lsum1, 2);
    const float li0 = 1.f / lsum0;
    const float li1 = 1.f / lsum1;

    const int r0 = 16 * w + g;
    float* ob = out + (size_t)b * CDIM * NDIM + n0;
    #pragma unroll
    for (int nf = 0; nf < 32; nf++) {
        int c = 8 * nf + 2 * t;
        float* d0 = ob + (size_t)c * NDIM + r0;
        float* d1 = d0 + NDIM;
        d0[0] += hacc[nf][0] * li0;
        d1[0] += hacc[nf][1] * li0;
        d0[8] += hacc[nf][2] * li1;
        d1[8] += hacc[nf][3] * li1;
    }
}

extern "C" void kernel_launch(void* const* d_in, const int* in_sizes, int n_in,
                              void* d_out, int out_size)
{
    const float* x  = (const float*)d_in[0];
    const float* Wq = (const float*)d_in[1];
    const float* bq = (const float*)d_in[2];
    const float* Wk = (const float*)d_in[3];
    const float* bk = (const float*)d_in[4];
    const float* Wv = (const float*)d_in[5];
    const float* bv = (const float*)d_in[6];
    const float* Wp = (const float*)d_in[7];
    const float* bp = (const float*)d_in[8];
    float* out = (float*)d_out;

    cudaFuncSetAttribute(proj2_kernel,
                         cudaFuncAttributeMaxDynamicSharedMemorySize, P2_BYTES);
    cudaFuncSetAttribute(attn_kernel,
                         cudaFuncAttributeMaxDynamicSharedMemorySize, SM_BYTES);

    xpose_kernel<<<dim3(64, 4, 8), 256>>>(x);
    wconv_kernel<<<dim3(4, 64), 256>>>(Wq, Wk, Wv, Wp);
    proj2_kernel<<<dim3(32, 4, 8), 256, P2_BYTES>>>(bq, bk, bv, bp, out);
    attn_kernel<<<dim3(NDIM / QR, BDIM), 256, SM_BYTES>>>(out);
}

// round 12
// speedup vs baseline: 10.1008x; 1.0367x over previous
#include <cuda_runtime.h>
#include <cuda_bf16.h>
#include <math.h>
#include <stdint.h>

#define CDIM 256
#define NDIM 4096
#define BDIM 8
#define QR   128
#define TK   64
#define NT   (NDIM / TK)   // 64

__device__ __nv_bfloat16 g_q[(size_t)BDIM * NDIM * CDIM];   // [b][n][c]
__device__ __nv_bfloat16 g_k[(size_t)BDIM * NDIM * CDIM];   // [b][n][c]
__device__ __nv_bfloat16 g_v[(size_t)BDIM * NDIM * CDIM];   // [b][c][n] (transposed)
__device__ __nv_bfloat16 g_xh[(size_t)BDIM * NDIM * CDIM];  // x^T hi [b][n][c]
__device__ __nv_bfloat16 g_xl[(size_t)BDIM * NDIM * CDIM];  // x^T lo
__device__ __nv_bfloat16 g_wh[4 * CDIM * CDIM];             // W hi [p][o][c]
__device__ __nv_bfloat16 g_wl[4 * CDIM * CDIM];             // W lo

// ---- attn smem byte offsets (tile swizzle: 16B chunk ^= row&7) ----
#define SQ_OFF 0u          // 128 x 256 bf16 = 64KB
#define SK_OFF 65536u      // 2 x (64 x 256 bf16) = 64KB
#define SV_OFF 131072u     // 2 x (256 x 64 bf16) = 64KB
#define SM_BYTES 196608u

// ---- proj2 smem byte offsets (per buffer; 2 buffers) ----
#define P2_XH 0u           // 128n x 64c bf16 (row 128B, 8 chunks)
#define P2_XL 16384u       // only loaded for p=3
#define P2_WH 32768u       // 256o x 64c bf16
#define P2_WL 65536u       // only loaded for p=3
#define P2_BUF 98304u
#define P2_BYTES 196608u

// ---------------- helpers ----------------
__device__ __forceinline__ uint32_t smem_u32(const void* p) {
    uint32_t a;
    asm("{ .reg .u64 t; cvta.to.shared.u64 t, %1; cvt.u32.u64 %0, t; }" : "=r"(a) : "l"(p));
    return a;
}
__device__ __forceinline__ float ex2(float x) {
    float y; asm("ex2.approx.f32 %0, %1;" : "=f"(y) : "f"(x)); return y;
}
__device__ __forceinline__ uint32_t bf2(float lo, float hi) {
    __nv_bfloat162 h = __float22bfloat162_rn(make_float2(lo, hi));
    return *(uint32_t*)&h;
}
__device__ __forceinline__ void cp16(uint32_t saddr, const void* gaddr) {
    asm volatile("cp.async.cg.shared.global [%0], [%1], 16;" :: "r"(saddr), "l"(gaddr));
}
__device__ __forceinline__ void cp_commit() {
    asm volatile("cp.async.commit_group;" ::: "memory");
}
template <int N>
__device__ __forceinline__ void cp_wait() {
    asm volatile("cp.async.wait_group %0;" :: "n"(N) : "memory");
}
__device__ __forceinline__ void ldm4(uint32_t* r, uint32_t addr) {
    asm volatile("ldmatrix.sync.aligned.m8n8.x4.shared.b16 {%0,%1,%2,%3}, [%4];"
        : "=r"(r[0]), "=r"(r[1]), "=r"(r[2]), "=r"(r[3]) : "r"(addr));
}
__device__ __forceinline__ void mma16(float* d, const uint32_t* a, uint32_t b0, uint32_t b1) {
    asm volatile("mma.sync.aligned.m16n8k16.row.col.f32.bf16.bf16.f32 "
        "{%0,%1,%2,%3}, {%4,%5,%6,%7}, {%8,%9}, {%0,%1,%2,%3};"
        : "+f"(d[0]), "+f"(d[1]), "+f"(d[2]), "+f"(d[3])
        : "r"(a[0]), "r"(a[1]), "r"(a[2]), "r"(a[3]), "r"(b0), "r"(b1));
}

// ---------------- x transpose + hi/lo bf16 split ----------------------------
__global__ __launch_bounds__(256) void xpose_kernel(const float* __restrict__ x)
{
    __shared__ float sm[64 * 65];
    const int n0 = blockIdx.x * 64;
    const int c0 = blockIdx.y * 64;
    const int b  = blockIdx.z;
    const int tid = threadIdx.x;

    const float* xb = x + ((size_t)b * CDIM + c0) * NDIM + n0;
    #pragma unroll
    for (int j = 0; j < 4; j++) {
        int idx = tid + 256 * j;
        int cc = idx >> 4, nn4 = idx & 15;
        float4 v = *(const float4*)(xb + (size_t)cc * NDIM + nn4 * 4);
        float* s = sm + cc * 65 + nn4 * 4;
        s[0] = v.x; s[1] = v.y; s[2] = v.z; s[3] = v.w;
    }
    __syncthreads();
    __nv_bfloat16* dh = g_xh + ((size_t)b * NDIM + n0) * CDIM + c0;
    __nv_bfloat16* dl = g_xl + ((size_t)b * NDIM + n0) * CDIM + c0;
    #pragma unroll
    for (int j = 0; j < 8; j++) {
        int idx = tid + 256 * j;
        int nn = idx >> 5, cp = idx & 31;
        float f0 = sm[(2 * cp)     * 65 + nn];
        float f1 = sm[(2 * cp + 1) * 65 + nn];
        float h0 = __bfloat162float(__float2bfloat16(f0));
        float h1 = __bfloat162float(__float2bfloat16(f1));
        *(uint32_t*)(dh + (size_t)nn * CDIM + 2 * cp) = bf2(f0, f1);
        *(uint32_t*)(dl + (size_t)nn * CDIM + 2 * cp) = bf2(f0 - h0, f1 - h1);
    }
}

// ---------------- W hi/lo convert ----------------
__global__ __launch_bounds__(256) void wconv_kernel(
    const float* __restrict__ Wq, const float* __restrict__ Wk,
    const float* __restrict__ Wv, const float* __restrict__ Wp)
{
    const int p = blockIdx.x;
    const float* W = (p == 0) ? Wq : (p == 1) ? Wk : (p == 2) ? Wv : Wp;
    int idx4 = blockIdx.y * 256 + threadIdx.x;
    float4 v = *(const float4*)(W + idx4 * 4);
    float hx = __bfloat162float(__float2bfloat16(v.x));
    float hy = __bfloat162float(__float2bfloat16(v.y));
    float hz = __bfloat162float(__float2bfloat16(v.z));
    float hw = __bfloat162float(__float2bfloat16(v.w));
    uint2 uh = make_uint2(bf2(v.x, v.y), bf2(v.z, v.w));
    uint2 ul = make_uint2(bf2(v.x - hx, v.y - hy), bf2(v.z - hz, v.w - hw));
    *(uint2*)(g_wh + (size_t)p * CDIM * CDIM + idx4 * 4) = uh;
    *(uint2*)(g_wl + (size_t)p * CDIM * CDIM + idx4 * 4) = ul;
}

// ---------------- proj2: bf16 mma projections -------------------------------
// grid (32 n-tiles, 4 p, 8 b), 256 thr. CTA: 128n x 256o, K chunks of 64.
// p<2 (q,k): D[n][o] = Xh*Wh (single chain; result stored bf16 anyway)
// p=2 (v):   D[o][n] = Wh*Xh (single chain)
// p=3 (res): D[o][n] = Wh*Xh + Wh*Xl + Wl*Xh (3-term; fp32 output path)
__global__ __launch_bounds__(256, 1) void proj2_kernel(
    const float* __restrict__ bq, const float* __restrict__ bk,
    const float* __restrict__ bv, const float* __restrict__ bp,
    float* __restrict__ out)
{
    extern __shared__ char smc[];
    const uint32_t sm0 = smem_u32(smc);
    const int n0 = blockIdx.x * 128;
    const int p  = blockIdx.y;
    const int b  = blockIdx.z;
    const float* bias = (p == 0) ? bq : (p == 1) ? bk : (p == 2) ? bv : bp;
    const bool qk = (p < 2);
    const bool res = (p == 3);

    const int tid = threadIdx.x, lane = tid & 31, w = tid >> 5;
    const int g = lane >> 2, t = lane & 3;
    const int wm  = qk ? (w & 1) : (w >> 1);
    const int wn4 = qk ? (w >> 1) : (w & 1);

    const __nv_bfloat16* xh = g_xh + ((size_t)b * NDIM + n0) * CDIM;
    const __nv_bfloat16* xl = g_xl + ((size_t)b * NDIM + n0) * CDIM;
    const __nv_bfloat16* wh = g_wh + (size_t)p * CDIM * CDIM;
    const __nv_bfloat16* wl = g_wl + (size_t)p * CDIM * CDIM;

    auto load_chunk = [&](int kc, int buf) {
        const uint32_t base = sm0 + (uint32_t)buf * P2_BUF;
        #pragma unroll
        for (int j = 0; j < 4; j++) {      // XH: 128 x 8
            int idx = tid + 256 * j, r = idx >> 3, ch = idx & 7;
            uint32_t so = (uint32_t)r * 128u + (uint32_t)((ch ^ (r & 7)) << 4);
            cp16(base + P2_XH + so, xh + (size_t)r * CDIM + kc * 64 + ch * 8);
        }
        #pragma unroll
        for (int j = 0; j < 8; j++) {      // WH: 256 x 8
            int idx = tid + 256 * j, r = idx >> 3, ch = idx & 7;
            uint32_t so = (uint32_t)r * 128u + (uint32_t)((ch ^ (r & 7)) << 4);
            cp16(base + P2_WH + so, wh + (size_t)r * CDIM + kc * 64 + ch * 8);
        }
        if (res) {
            #pragma unroll
            for (int j = 0; j < 4; j++) {  // XL
                int idx = tid + 256 * j, r = idx >> 3, ch = idx & 7;
                uint32_t so = (uint32_t)r * 128u + (uint32_t)((ch ^ (r & 7)) << 4);
                cp16(base + P2_XL + so, xl + (size_t)r * CDIM + kc * 64 + ch * 8);
            }
            #pragma unroll
            for (int j = 0; j < 8; j++) {  // WL
                int idx = tid + 256 * j, r = idx >> 3, ch = idx & 7;
                uint32_t so = (uint32_t)r * 128u + (uint32_t)((ch ^ (r & 7)) << 4);
                cp16(base + P2_WL + so, wl + (size_t)r * CDIM + kc * 64 + ch * 8);
            }
        }
    };

    load_chunk(0, 0);
    cp_commit();

    const int rA  = ((lane >> 3) & 1) * 8 + (lane & 7);
    const int cAo = lane >> 4;
    const int rB_ = ((lane >> 4) & 1) * 8 + (lane & 7);
    const int cBo = (lane >> 3) & 1;
    const int xs  = lane & 7;

    float acc[4][8][4];
    #pragma unroll
    for (int mf = 0; mf < 4; mf++)
        #pragma unroll
        for (int nf = 0; nf < 8; nf++)
            #pragma unroll
            for (int k = 0; k < 4; k++) acc[mf][nf][k] = 0.f;

    for (int kc = 0; kc < 4; kc++) {
        const int buf = kc & 1;
        cp_wait<0>();
        __syncthreads();
        if (kc + 1 < 4) { load_chunk(kc + 1, buf ^ 1); cp_commit(); }

        const uint32_t base = sm0 + (uint32_t)buf * P2_BUF;
        const uint32_t offA1 = qk ? P2_XH : P2_WH;
        const uint32_t offB1 = qk ? P2_WH : P2_XH;
        const uint32_t aBase = base + (uint32_t)(64 * wm) * 128u + (uint32_t)rA * 128u;
        const uint32_t bBase = base + (uint32_t)(64 * wn4) * 128u + (uint32_t)rB_ * 128u;

        #pragma unroll
        for (int ks = 0; ks < 4; ks++) {
            const uint32_t ao = (uint32_t)(((2 * ks + cAo) ^ xs) << 4);
            const uint32_t bo = (uint32_t)(((2 * ks + cBo) ^ xs) << 4);
            uint32_t b1[4][4];
            #pragma unroll
            for (int nf2 = 0; nf2 < 4; nf2++)
                ldm4(b1[nf2], bBase + offB1 + (uint32_t)nf2 * 2048u + bo);
            if (!res) {
                // single chain: A1 x B1
                #pragma unroll
                for (int mf = 0; mf < 4; mf++) {
                    uint32_t ah[4];
                    ldm4(ah, aBase + offA1 + (uint32_t)mf * 2048u + ao);
                    #pragma unroll
                    for (int nf2 = 0; nf2 < 4; nf2++) {
                        mma16(acc[mf][2 * nf2],     ah, b1[nf2][0], b1[nf2][1]);
                        mma16(acc[mf][2 * nf2 + 1], ah, b1[nf2][2], b1[nf2][3]);
                    }
                }
            } else {
                // 3-term: Wh*Xh + Wh*Xl + Wl*Xh
                uint32_t b2[4][4];
                #pragma unroll
                for (int nf2 = 0; nf2 < 4; nf2++)
                    ldm4(b2[nf2], bBase + P2_XL + (uint32_t)nf2 * 2048u + bo);
                #pragma unroll
                for (int mf = 0; mf < 4; mf++) {
                    uint32_t ah[4], al[4];
                    ldm4(ah, aBase + P2_WH + (uint32_t)mf * 2048u + ao);
                    ldm4(al, aBase + P2_WL + (uint32_t)mf * 2048u + ao);
                    #pragma unroll
                    for (int nf2 = 0; nf2 < 4; nf2++) {
                        mma16(acc[mf][2 * nf2],     ah, b1[nf2][0], b1[nf2][1]);
                        mma16(acc[mf][2 * nf2 + 1], ah, b1[nf2][2], b1[nf2][3]);
                        mma16(acc[mf][2 * nf2],     ah, b2[nf2][0], b2[nf2][1]);
                        mma16(acc[mf][2 * nf2 + 1], ah, b2[nf2][2], b2[nf2][3]);
                        mma16(acc[mf][2 * nf2],     al, b1[nf2][0], b1[nf2][1]);
                        mma16(acc[mf][2 * nf2 + 1], al, b1[nf2][2], b1[nf2][3]);
                    }
                }
            }
        }
        __syncthreads();
    }

    if (qk) {
        __nv_bfloat16* dst = ((p == 0) ? g_q : g_k) + (size_t)b * NDIM * CDIM;
        #pragma unroll
        for (int mf = 0; mf < 4; mf++) {
            int n = n0 + 64 * wm + 16 * mf + g;
            #pragma unroll
            for (int nf = 0; nf < 8; nf++) {
                int o = 64 * wn4 + 8 * nf + 2 * t;
                float2 bs = *(const float2*)(bias + o);
                *(uint32_t*)(dst + (size_t)n * CDIM + o) =
                    bf2(acc[mf][nf][0] + bs.x, acc[mf][nf][1] + bs.y);
                *(uint32_t*)(dst + (size_t)(n + 8) * CDIM + o) =
                    bf2(acc[mf][nf][2] + bs.x, acc[mf][nf][3] + bs.y);
            }
        }
    } else if (p == 2) {
        __nv_bfloat16* dst = g_v + (size_t)b * CDIM * NDIM;
        #pragma unroll
        for (int mf = 0; mf < 4; mf++) {
            int o = 64 * wm + 16 * mf + g;
            float b0 = bias[o], b8 = bias[o + 8];
            #pragma unroll
            for (int nf = 0; nf < 8; nf++) {
                int n = n0 + 64 * wn4 + 8 * nf + 2 * t;
                *(uint32_t*)(dst + (size_t)o * NDIM + n) =
                    bf2(acc[mf][nf][0] + b0, acc[mf][nf][1] + b0);
                *(uint32_t*)(dst + (size_t)(o + 8) * NDIM + n) =
                    bf2(acc[mf][nf][2] + b8, acc[mf][nf][3] + b8);
            }
        }
    } else {
        float* dst = out + (size_t)b * CDIM * NDIM;
        #pragma unroll
        for (int mf = 0; mf < 4; mf++) {
            int o = 64 * wm + 16 * mf + g;
            float b0 = bias[o], b8 = bias[o + 8];
            #pragma unroll
            for (int nf = 0; nf < 8; nf++) {
                int n = n0 + 64 * wn4 + 8 * nf + 2 * t;
                *(float2*)(dst + (size_t)o * NDIM + n) =
                    make_float2(acc[mf][nf][0] + b0, acc[mf][nf][1] + b0);
                *(float2*)(dst + (size_t)(o + 8) * NDIM + n) =
                    make_float2(acc[mf][nf][2] + b8, acc[mf][nf][3] + b8);
            }
        }
    }
}

// ---------------- K/V tile loader (cp.async, bf16, swizzled) ---------------
__device__ __forceinline__ void load_kv(uint32_t sm0, const __nv_bfloat16* kb,
                                        const __nv_bfloat16* vb, int i, int buf, int tid)
{
    const int m0 = i * TK;
    const uint32_t sk = sm0 + SK_OFF + (uint32_t)buf * 32768u;
    const uint32_t sv = sm0 + SV_OFF + (uint32_t)buf * 32768u;
    #pragma unroll
    for (int j = 0; j < 8; j++) {          // K: 64 keys x 256 c
        int idx = tid + 256 * j, r = idx >> 5, ch = idx & 31;
        cp16(sk + (uint32_t)r * 512u + (uint32_t)((ch ^ (r & 7)) << 4),
             kb + (size_t)(m0 + r) * CDIM + ch * 8);
    }
    #pragma unroll
    for (int j = 0; j < 8; j++) {          // V^T: 256 c x 64 keys
        int idx = tid + 256 * j, r = idx >> 3, ch = idx & 7;
        cp16(sv + (uint32_t)r * 128u + (uint32_t)((ch ^ (r & 7)) << 4),
             vb + (size_t)r * NDIM + m0 + ch * 8);
    }
}

// ---------------- bf16 mma flash attention (unchanged from R10/R11) --------
__global__ __launch_bounds__(256, 1) void attn_kernel(float* __restrict__ out)
{
    extern __shared__ char smc[];
    const uint32_t sm0 = smem_u32(smc);
    const int tid = threadIdx.x, lane = tid & 31;
    const int w = tid >> 5;
    const int g = lane >> 2, t = lane & 3;
    const int b = blockIdx.y, n0 = blockIdx.x * QR;

    const __nv_bfloat16* qb = g_q + ((size_t)b * NDIM + n0) * CDIM;
    const __nv_bfloat16* kb = g_k + (size_t)b * NDIM * CDIM;
    const __nv_bfloat16* vb = g_v + (size_t)b * CDIM * NDIM;

    #pragma unroll
    for (int j = 0; j < 16; j++) {
        int idx = tid + 256 * j, r = idx >> 5, ch = idx & 31;
        cp16(sm0 + SQ_OFF + (uint32_t)r * 512u + (uint32_t)((ch ^ (r & 7)) << 4),
             qb + (size_t)r * CDIM + ch * 8);
    }
    load_kv(sm0, kb, vb, 0, 0, tid);
    cp_commit();

    const int rA  = ((lane >> 3) & 1) * 8 + (lane & 7);
    const int cAo = lane >> 4;
    const int rB_ = ((lane >> 4) & 1) * 8 + (lane & 7);
    const int cBo = (lane >> 3) & 1;
    const int xs  = lane & 7;
    const uint32_t qA = sm0 + SQ_OFF + (uint32_t)(16 * w + rA) * 512u;

    float hacc[32][4];
    #pragma unroll
    for (int nf = 0; nf < 32; nf++)
        #pragma unroll
        for (int k = 0; k < 4; k++) hacc[nf][k] = 0.f;
    float lsum0 = 0.f, lsum1 = 0.f;
    const float EC = 0.0901684400555602f;    // log2(e)/16

    for (int i = 0; i < NT; i++) {
        const int buf = i & 1;
        cp_wait<0>();
        __syncthreads();
        if (i + 1 < NT) { load_kv(sm0, kb, vb, i + 1, buf ^ 1, tid); cp_commit(); }

        float sacc[8][4];
        #pragma unroll
        for (int f = 0; f < 8; f++)
            #pragma unroll
            for (int k = 0; k < 4; k++) sacc[f][k] = 0.f;
        const uint32_t kB = sm0 + SK_OFF + (uint32_t)buf * 32768u
                          + (uint32_t)rB_ * 512u;
        #pragma unroll
        for (int ks = 0; ks < 16; ks++) {
            uint32_t aq[4];
            ldm4(aq, qA + (uint32_t)(((2 * ks + cAo) ^ xs) << 4));
            uint32_t ko = (uint32_t)(((2 * ks + cBo) ^ xs) << 4);
            #pragma unroll
            for (int nf2 = 0; nf2 < 4; nf2++) {
                uint32_t bk[4];
                ldm4(bk, kB + (uint32_t)nf2 * 8192u + ko);
                mma16(sacc[2 * nf2],     aq, bk[0], bk[1]);
                mma16(sacc[2 * nf2 + 1], aq, bk[2], bk[3]);
            }
        }

        uint32_t pf[4][4];
        #pragma unroll
        for (int nf = 0; nf < 8; nf++) {
            float e0 = ex2(sacc[nf][0] * EC);
            float e1 = ex2(sacc[nf][1] * EC);
            float e2 = ex2(sacc[nf][2] * EC);
            float e3 = ex2(sacc[nf][3] * EC);
            lsum0 += e0 + e1;
            lsum1 += e2 + e3;
            pf[nf >> 1][(nf & 1) * 2 + 0] = bf2(e0, e1);
            pf[nf >> 1][(nf & 1) * 2 + 1] = bf2(e2, e3);
        }

        const uint32_t vB = sm0 + SV_OFF + (uint32_t)buf * 32768u
                          + (uint32_t)rB_ * 128u;
        #pragma unroll
        for (int ks = 0; ks < 4; ks++) {
            uint32_t vo = (uint32_t)(((2 * ks + cBo) ^ xs) << 4);
            #pragma unroll
            for (int nb = 0; nb < 16; nb++) {
                uint32_t bv[4];
                ldm4(bv, vB + (uint32_t)nb * 2048u + vo);
                mma16(hacc[2 * nb],     pf[ks], bv[0], bv[1]);
                mma16(hacc[2 * nb + 1], pf[ks], bv[2], bv[3]);
            }
        }
    }

    lsum0 += __shfl_xor_sync(0xffffffffu, lsum0, 1);
    lsum0 += __shfl_xor_sync(0xffffffffu, lsum0, 2);
    lsum1 += __shfl_xor_sync(0xffffffffu, lsum1, 1);
    lsum1 += __shfl_xor_sync(0xffffffffu, lsum1, 2);
    const float li0 = 1.f / lsum0;
    const float li1 = 1.f / lsum1;

    const int r0 = 16 * w + g;
    float* ob = out + (size_t)b * CDIM * NDIM + n0;
    #pragma unroll
    for (int nf = 0; nf < 32; nf++) {
        int c = 8 * nf + 2 * t;
        float* d0 = ob + (size_t)c * NDIM + r0;
        float* d1 = d0 + NDIM;
        d0[0] += hacc[nf][0] * li0;
        d1[0] += hacc[nf][1] * li0;
        d0[8] += hacc[nf][2] * li1;
        d1[8] += hacc[nf][3] * li1;
    }
}

extern "C" void kernel_launch(void* const* d_in, const int* in_sizes, int n_in,
                              void* d_out, int out_size)
{
    const float* x  = (const float*)d_in[0];
    const float* Wq = (const float*)d_in[1];
    const float* bq = (const float*)d_in[2];
    const float* Wk = (const float*)d_in[3];
    const float* bk = (const float*)d_in[4];
    const float* Wv = (const float*)d_in[5];
    const float* bv = (const float*)d_in[6];
    const float* Wp = (const float*)d_in[7];
    const float* bp = (const float*)d_in[8];
    float* out = (float*)d_out;

    cudaFuncSetAttribute(proj2_kernel,
                         cudaFuncAttributeMaxDynamicSharedMemorySize, P2_BYTES);
    cudaFuncSetAttribute(attn_kernel,
                         cudaFuncAttributeMaxDynamicSharedMemorySize, SM_BYTES);

    xpose_kernel<<<dim3(64, 4, 8), 256>>>(x);
    wconv_kernel<<<dim3(4, 64), 256>>>(Wq, Wk, Wv, Wp);
    proj2_kernel<<<dim3(32, 4, 8), 256, P2_BYTES>>>(bq, bk, bv, bp, out);
    attn_kernel<<<dim3(NDIM / QR, BDIM), 256, SM_BYTES>>>(out);
}